// round 7
// baseline (speedup 1.0000x reference)
#include <cuda_runtime.h>
#include <cstdint>
#include <cstddef>

typedef unsigned short ushort_t;

#define NTOK 8192
#define EEXP 16
#define CAPS 640
#define RBLKS (NTOK/8)

// ---------------- static device scratch ----------------
__device__ ushort_t g_xhi[(size_t)NTOK * 1024];
__device__ ushort_t g_xlo[(size_t)NTOK * 1024];
__device__ ushort_t g_hhi[(size_t)EEXP * CAPS * 4096];
__device__ ushort_t g_hlo[(size_t)EEXP * CAPS * 4096];
__device__ float g_gate[NTOK];
__device__ int   g_eid[NTOK];
__device__ int   g_cnt[EEXP];
__device__ int   g_lst_tok[EEXP * NTOK];
__device__ float g_lst_gate[EEXP * NTOK];
__device__ int   g_tok4slot[EEXP * CAPS];
__device__ float g_slotgate[EEXP * CAPS];
__device__ float g_pp[RBLKS * 16];
__device__ int   g_pf[RBLKS * 16];
__device__ float g_pz[RBLKS];
__device__ int   g_pn[RBLKS];

// ---------------- helpers ----------------
__device__ __forceinline__ uint32_t f2bf(float f) {
    uint32_t x = __float_as_uint(f);
    return (x + 0x7FFFu + ((x >> 16) & 1u)) >> 16;
}
__device__ __forceinline__ float bf2f(uint32_t b) { return __uint_as_float(b << 16); }
__device__ __forceinline__ uint32_t smem_u32(const void* p) {
    uint32_t a;
    asm("{ .reg .u64 t; cvta.to.shared.u64 t, %1; cvt.u32.u64 %0, t; }" : "=r"(a) : "l"(p));
    return a;
}
__device__ __forceinline__ void cpa16(uint32_t d, const void* s) {
    asm volatile("cp.async.cg.shared.global [%0], [%1], 16;" :: "r"(d), "l"(s));
}
__device__ __forceinline__ void cp_commit() { asm volatile("cp.async.commit_group;"); }
__device__ __forceinline__ void cp_wait0() { asm volatile("cp.async.wait_group 0;" ::: "memory"); }
__device__ __forceinline__ void ldsm4(uint32_t* r, uint32_t a) {
    asm volatile("ldmatrix.sync.aligned.m8n8.x4.shared.b16 {%0,%1,%2,%3}, [%4];"
        : "=r"(r[0]), "=r"(r[1]), "=r"(r[2]), "=r"(r[3]) : "r"(a));
}
__device__ __forceinline__ void ldsm4t(uint32_t* r, uint32_t a) {
    asm volatile("ldmatrix.sync.aligned.m8n8.x4.trans.shared.b16 {%0,%1,%2,%3}, [%4];"
        : "=r"(r[0]), "=r"(r[1]), "=r"(r[2]), "=r"(r[3]) : "r"(a));
}
__device__ __forceinline__ void mma16816(float* c, const uint32_t* a, uint32_t b0, uint32_t b1) {
    asm volatile("mma.sync.aligned.m16n8k16.row.col.f32.bf16.bf16.f32 "
        "{%0,%1,%2,%3}, {%4,%5,%6,%7}, {%8,%9}, {%0,%1,%2,%3};"
        : "+f"(c[0]), "+f"(c[1]), "+f"(c[2]), "+f"(c[3])
        : "r"(a[0]), "r"(a[1]), "r"(a[2]), "r"(a[3]), "r"(b0), "r"(b1));
}

// ---------------- init: zero y + expert counters ----------------
__global__ void init_kernel(float* __restrict__ out, long ytot) {
    if (blockIdx.x == 0 && threadIdx.x < EEXP) g_cnt[threadIdx.x] = 0;
    long i4 = (long)blockIdx.x * blockDim.x + threadIdx.x;
    long n4 = ytot >> 2;
    long stride = (long)gridDim.x * blockDim.x;
    float4 z = make_float4(0.f, 0.f, 0.f, 0.f);
    for (; i4 < n4; i4 += stride) reinterpret_cast<float4*>(out)[i4] = z;
}

// ---------------- bf16 split pack for x ----------------
__global__ void pack_kernel(const float* __restrict__ in, ushort_t* __restrict__ hi,
                            ushort_t* __restrict__ lo, long n4)
{
    long i = (long)blockIdx.x * blockDim.x + threadIdx.x;
    long stride = (long)gridDim.x * blockDim.x;
    for (; i < n4; i += stride) {
        float4 v = reinterpret_cast<const float4*>(in)[i];
        uint32_t hx = f2bf(v.x), hy = f2bf(v.y), hz = f2bf(v.z), hw = f2bf(v.w);
        uint32_t lx = f2bf(v.x - bf2f(hx)), ly = f2bf(v.y - bf2f(hy));
        uint32_t lz = f2bf(v.z - bf2f(hz)), lw = f2bf(v.w - bf2f(hw));
        reinterpret_cast<uint2*>(hi)[i] = make_uint2(hx | (hy << 16), hz | (hw << 16));
        reinterpret_cast<uint2*>(lo)[i] = make_uint2(lx | (ly << 16), lz | (lw << 16));
    }
}

// ---------------- router ----------------
__global__ void __launch_bounds__(256) router_kernel(
    const float* __restrict__ x, const int* __restrict__ mask,
    const float* __restrict__ noise, const float* __restrict__ Wr, int N, int D)
{
    int warp = threadIdx.x >> 5, lane = threadIdx.x & 31;
    int t = blockIdx.x * 8 + warp;
    __shared__ float s_log[8][16];
    __shared__ float s_p[16]; __shared__ int s_f[16];
    __shared__ float s_z; __shared__ int s_n;
    if (threadIdx.x < 16) { s_p[threadIdx.x] = 0.f; s_f[threadIdx.x] = 0; }
    if (threadIdx.x == 0) { s_z = 0.f; s_n = 0; }
    __syncthreads();
    if (t < N) {
        float acc[16];
#pragma unroll
        for (int e = 0; e < 16; ++e) acc[e] = 0.f;
        const float* xr = x + (size_t)t * D;
        for (int d = lane; d < D; d += 32) {
            float xv = xr[d];
            const float* w = Wr + (size_t)d * 16;
#pragma unroll
            for (int e = 0; e < 16; ++e) acc[e] = fmaf(xv, w[e], acc[e]);
        }
#pragma unroll
        for (int e = 0; e < 16; ++e) {
            float v = acc[e];
#pragma unroll
            for (int o = 16; o; o >>= 1) v += __shfl_xor_sync(0xFFFFFFFFu, v, o);
            if (lane == 0) s_log[warp][e] = v;
        }
        __syncwarp();
        int e = lane & 15;
        float lc = s_log[warp][e];
        int mk = mask[t] ? 1 : 0;
        float nz = noise[(size_t)t * 16 + e];
        float mult = mk ? (1.0f + (nz * 2.0f - 1.0f) * 0.1f) : 1.0f;
        float ln = lc * mult;
        float mx = ln;
#pragma unroll
        for (int o = 8; o; o >>= 1) mx = fmaxf(mx, __shfl_xor_sync(0xFFFFFFFFu, mx, o, 16));
        unsigned bal = __ballot_sync(0xFFFFFFFFu, ln == mx);
        int eid = __ffs(bal) - 1;
        float se = expf(ln - mx);
#pragma unroll
        for (int o = 8; o; o >>= 1) se += __shfl_xor_sync(0xFFFFFFFFu, se, o, 16);
        float lse = mx + logf(se);
        float gate = expf(mx - lse);
        float mxc = lc;
#pragma unroll
        for (int o = 8; o; o >>= 1) mxc = fmaxf(mxc, __shfl_xor_sync(0xFFFFFFFFu, mxc, o, 16));
        unsigned balc = __ballot_sync(0xFFFFFFFFu, lc == mxc);
        int eidc = __ffs(balc) - 1;
        float sec = expf(lc - mxc);
#pragma unroll
        for (int o = 8; o; o >>= 1) sec += __shfl_xor_sync(0xFFFFFFFFu, sec, o, 16);
        float lsec = mxc + logf(sec);
        float pce = expf(lc - lsec);
        if (lane < 16 && mk) {
            atomicAdd(&s_p[e], pce);
            if (e == eidc) atomicAdd(&s_f[e], 1);
        }
        if (lane == 0) {
            g_gate[t] = gate; g_eid[t] = eid;
            if (mk) { atomicAdd(&s_z, lsec * lsec); atomicAdd(&s_n, 1); }
        }
    }
    __syncthreads();
    if (threadIdx.x < 16) {
        g_pp[blockIdx.x * 16 + threadIdx.x] = s_p[threadIdx.x];
        g_pf[blockIdx.x * 16 + threadIdx.x] = s_f[threadIdx.x];
    }
    if (threadIdx.x == 0) { g_pz[blockIdx.x] = s_z; g_pn[blockIdx.x] = s_n; }
}

__global__ void loss_reduce_kernel(float* __restrict__ out, int nb, long outsz) {
    __shared__ float sp[16], sf[16], szn[2];
    int tid = threadIdx.x;
    if (tid < 16) {
        float s = 0.f; int c = 0;
        for (int b = 0; b < nb; ++b) { s += g_pp[b * 16 + tid]; c += g_pf[b * 16 + tid]; }
        sp[tid] = s; sf[tid] = (float)c;
    }
    if (tid == 16) { float s = 0.f; for (int b = 0; b < nb; ++b) s += g_pz[b]; szn[0] = s; }
    if (tid == 17) { int c = 0; for (int b = 0; b < nb; ++b) c += g_pn[b]; szn[1] = (float)c; }
    __syncthreads();
    if (tid == 0) {
        float n = szn[1], lb = 0.f;
        for (int e = 0; e < 16; ++e) lb += (sp[e] / n) * (sf[e] / n);
        out[outsz - 2] = lb * 16.0f;
        out[outsz - 1] = szn[0] / n;
    }
}

// ---------------- dispatch: parallel scan + per-expert rank ----------------
__global__ void __launch_bounds__(256) scan_kernel(const int* __restrict__ mask, int N)
{
    int t = blockIdx.x * blockDim.x + threadIdx.x;
    if (t < N && mask[t]) {
        int e = g_eid[t];
        int i = atomicAdd(&g_cnt[e], 1);
        g_lst_tok[e * NTOK + i] = t;
        g_lst_gate[e * NTOK + i] = g_gate[t];
    }
}

__global__ void __launch_bounds__(256) rank_kernel(int cap)
{
    extern __shared__ char dsm[];
    float* sg = (float*)dsm;
    int*   st = (int*)(dsm + (size_t)NTOK * 4);
    int e = blockIdx.x, tid = threadIdx.x;
    for (int i = tid; i < cap; i += 256) {
        g_tok4slot[e * cap + i] = -1;
        g_slotgate[e * cap + i] = 0.f;
    }
    int cnt = g_cnt[e];
    for (int i = tid; i < cnt; i += 256) {
        st[i] = g_lst_tok[e * NTOK + i];
        sg[i] = g_lst_gate[e * NTOK + i];
    }
    __syncthreads();
    for (int i = tid; i < cnt; i += 256) {
        int ti = st[i]; float gi = sg[i];
        int r = 0;
        for (int j = 0; j < cnt; ++j) {
            float gj = sg[j]; int tj = st[j];
            r += (gj > gi) || (gj == gi && tj < ti);
        }
        if (r < cap) {
            g_tok4slot[e * cap + r] = ti;
            g_slotgate[e * cap + r] = gi;
        }
    }
}

// ---------------- bf16-split tensor-core GEMM (mma.sync), fp32 B in-kernel ----
// CTA tile 128m x 128n, BK=32, 8 warps (4m x 2n), warp tile 32x64.
// B (weights) loaded fp32 via cp.async staging, converted to hi/lo in-kernel.
// MODE 0: h = relu(gather(x) @ W1[e]); A packed from g_x{hi,lo}
// MODE 1: y = (h @ W2[e]) * gate;      A packed from g_h{hi,lo}
#define ABUF(buf, s) ((buf) * 20480 + (s) * 10240)
#define BCV(buf, s)  (40960 + (buf) * 16384 + (s) * 8192)
#define BST(buf)     (73728 + (buf) * 16896)
#define BST_PITCH 528
#define GSMEM (73728 + 2 * 16896)

template<int MODE>
__global__ void __launch_bounds__(256, 2) gemm_kernel(
    const float* __restrict__ Bw, float* __restrict__ y, int cap)
{
    const int K   = (MODE == 0) ? 1024 : 4096;
    const int NT  = (MODE == 0) ? 32 : 8;
    const int Nn  = (MODE == 0) ? 4096 : 1024;
    const int NCH = K / 32;

    int b = blockIdx.x;
    const int m  = b % 5; b /= 5;
    const int n  = b % NT;
    const int e  = b / NT;
    const int m0 = m * 128, n0 = n * 128;

    extern __shared__ char smem[];
    const uint32_t sb = smem_u32(smem);
    __shared__ int s_arow[128];

    const int tid = threadIdx.x, wid = tid >> 5, lane = tid & 31;
    const int wm = wid & 3, wn = wid >> 2;

    if (tid < 128) {
        if (MODE == 0) {
            int tok = g_tok4slot[e * cap + m0 + tid];
            s_arow[tid] = (tok >= 0) ? tok : 0;
        } else {
            s_arow[tid] = e * CAPS + m0 + tid;
        }
    }
    __syncthreads();

    const ushort_t* AHI = (MODE == 0) ? g_xhi : g_hhi;
    const ushort_t* ALO = (MODE == 0) ? g_xlo : g_hlo;
    const float* Bf = Bw + (size_t)e * K * Nn;

    // A cp.async coordinates (packed bf16 hi/lo, row pitch K elems)
    const int ar0 = tid >> 2, ac0 = tid & 3;
    const int ar1 = (tid + 256) >> 2;
    const ushort_t* aHi0 = AHI + (size_t)s_arow[ar0] * K + ac0 * 8;
    const ushort_t* aLo0 = ALO + (size_t)s_arow[ar0] * K + ac0 * 8;
    const ushort_t* aHi1 = AHI + (size_t)s_arow[ar1] * K + ac0 * 8;
    const ushort_t* aLo1 = ALO + (size_t)s_arow[ar1] * K + ac0 * 8;
    const uint32_t aoff0 = ar0 * 80 + ac0 * 16, aoff1 = ar1 * 80 + ac0 * 16;

    // B fp32 staging coordinates: thread owns row rs, 16 consecutive floats
    const int rs = tid >> 3, c8 = tid & 7;   // rs 0..31, c8 0..7
    const float* bsrc = Bf + (size_t)rs * Nn + n0 + c8 * 16;
    const uint32_t bstg = rs * BST_PITCH + c8 * 64;

    float acc[2][8][4];
#pragma unroll
    for (int i = 0; i < 2; ++i)
#pragma unroll
        for (int j = 0; j < 8; ++j)
#pragma unroll
            for (int q = 0; q < 4; ++q) acc[i][j][q] = 0.f;

    auto issue = [&](int kt, int buf) {
        const long ka = (long)kt * 32;
        cpa16(sb + ABUF(buf, 0) + aoff0, aHi0 + ka);
        cpa16(sb + ABUF(buf, 0) + aoff1, aHi1 + ka);
        cpa16(sb + ABUF(buf, 1) + aoff0, aLo0 + ka);
        cpa16(sb + ABUF(buf, 1) + aoff1, aLo1 + ka);
        const float* bs = bsrc + (size_t)kt * 32 * Nn;
        const uint32_t bd = sb + BST(buf) + bstg;
#pragma unroll
        for (int j = 0; j < 4; ++j) cpa16(bd + j * 16, bs + j * 4);
        cp_commit();
    };

    issue(0, 0);

    const uint32_t a_row = (lane & 15), a_kq = (lane >> 4);
    const uint32_t b_kr = (lane & 7) + (lane >> 4) * 8;
    const uint32_t b_nc = wn * 8 + ((lane >> 3) & 1);

    for (int kt = 0; kt < NCH; ++kt) {
        const int buf = kt & 1;
        cp_wait0();

        // convert own staged fp32 -> swizzled bf16 hi/lo tiles
        {
            const char* src = smem + BST(buf) + bstg;
            char* bh = smem + BCV(buf, 0);
            char* bl = smem + BCV(buf, 1);
#pragma unroll
            for (int p = 0; p < 2; ++p) {
                float4 v0 = *(const float4*)(src + p * 32);
                float4 v1 = *(const float4*)(src + p * 32 + 16);
                uint32_t h0 = f2bf(v0.x), h1 = f2bf(v0.y), h2 = f2bf(v0.z), h3 = f2bf(v0.w);
                uint32_t h4 = f2bf(v1.x), h5 = f2bf(v1.y), h6 = f2bf(v1.z), h7 = f2bf(v1.w);
                uint4 hv = make_uint4(h0 | (h1 << 16), h2 | (h3 << 16),
                                      h4 | (h5 << 16), h6 | (h7 << 16));
                uint4 lv = make_uint4(
                    f2bf(v0.x - bf2f(h0)) | (f2bf(v0.y - bf2f(h1)) << 16),
                    f2bf(v0.z - bf2f(h2)) | (f2bf(v0.w - bf2f(h3)) << 16),
                    f2bf(v1.x - bf2f(h4)) | (f2bf(v1.y - bf2f(h5)) << 16),
                    f2bf(v1.z - bf2f(h6)) | (f2bf(v1.w - bf2f(h7)) << 16));
                uint32_t nc = c8 * 2 + p;
                uint32_t off = rs * 256 + ((nc ^ (rs & 7)) << 4);
                *(uint4*)(bh + off) = hv;
                *(uint4*)(bl + off) = lv;
            }
        }
        __syncthreads();
        if (kt + 1 < NCH) issue(kt + 1, buf ^ 1);

        const uint32_t aH = sb + ABUF(buf, 0), aL = sb + ABUF(buf, 1);
        const uint32_t bH = sb + BCV(buf, 0), bL = sb + BCV(buf, 1);

#pragma unroll
        for (int ks = 0; ks < 2; ++ks) {
            uint32_t fAH[2][4], fAL[2][4];
#pragma unroll
            for (int tm = 0; tm < 2; ++tm) {
                uint32_t ao = (wm * 32 + tm * 16 + a_row) * 80 + (ks * 16 + a_kq * 8) * 2;
                ldsm4(fAH[tm], aH + ao);
                ldsm4(fAL[tm], aL + ao);
            }
            const uint32_t kr = ks * 16 + b_kr;
            const uint32_t krl = kr & 7;
#pragma unroll
            for (int nb = 0; nb < 4; ++nb) {
                uint32_t nc = b_nc + nb * 2;
                uint32_t bo = kr * 256 + ((nc ^ krl) << 4);
                uint32_t fBH[4], fBL[4];
                ldsm4t(fBH, bH + bo);
                ldsm4t(fBL, bL + bo);
#pragma unroll
                for (int tm = 0; tm < 2; ++tm) {
                    mma16816(acc[tm][nb * 2 + 0], fAH[tm], fBH[0], fBH[2]);
                    mma16816(acc[tm][nb * 2 + 1], fAH[tm], fBH[1], fBH[3]);
                    mma16816(acc[tm][nb * 2 + 0], fAH[tm], fBL[0], fBL[2]);
                    mma16816(acc[tm][nb * 2 + 1], fAH[tm], fBL[1], fBL[3]);
                    mma16816(acc[tm][nb * 2 + 0], fAL[tm], fBH[0], fBH[2]);
                    mma16816(acc[tm][nb * 2 + 1], fAL[tm], fBH[1], fBH[3]);
                }
            }
        }
        __syncthreads();
    }

    // ---- epilogue ----
    const int gid = lane >> 2, tig = lane & 3;
#pragma unroll
    for (int tm = 0; tm < 2; ++tm) {
        const int r0 = m0 + wm * 32 + tm * 16 + gid;
#pragma unroll
        for (int j = 0; j < 8; ++j) {
            const int col = n0 + wn * 64 + j * 8 + tig * 2;
            if (MODE == 0) {
#pragma unroll
                for (int hh = 0; hh < 2; ++hh) {
                    int row = r0 + hh * 8;
                    float v0 = fmaxf(acc[tm][j][hh * 2 + 0], 0.f);
                    float v1 = fmaxf(acc[tm][j][hh * 2 + 1], 0.f);
                    uint32_t h0 = f2bf(v0), h1 = f2bf(v1);
                    uint32_t l0 = f2bf(v0 - bf2f(h0)), l1 = f2bf(v1 - bf2f(h1));
                    size_t idx = (size_t)(e * CAPS + row) * 4096 + col;
                    *(uint32_t*)(g_hhi + idx) = h0 | (h1 << 16);
                    *(uint32_t*)(g_hlo + idx) = l0 | (l1 << 16);
                }
            } else {
#pragma unroll
                for (int hh = 0; hh < 2; ++hh) {
                    int row = r0 + hh * 8;
                    int slot = e * cap + row;
                    int tok = g_tok4slot[slot];
                    if (tok >= 0) {
                        float g = g_slotgate[slot];
                        float2 v;
                        v.x = acc[tm][j][hh * 2 + 0] * g;
                        v.y = acc[tm][j][hh * 2 + 1] * g;
                        *(float2*)(y + (size_t)tok * 1024 + col) = v;
                    }
                }
            }
        }
    }
}

// ---------------- launch ----------------
extern "C" void kernel_launch(void* const* d_in, const int* in_sizes, int n_in,
                              void* d_out, int out_size)
{
    const float* x     = (const float*)d_in[0];
    const int*   mask  = (const int*)d_in[1];
    const float* noise = (const float*)d_in[2];
    const float* Wr    = (const float*)d_in[3];
    const float* W1    = (const float*)d_in[4];
    const float* W2    = (const float*)d_in[5];
    float*       out   = (float*)d_out;

    const int  N = in_sizes[1];                      // 8192
    const int  D = in_sizes[0] / N;                  // 1024
    const int  E = in_sizes[2] / N;                  // 16
    const int  H = (int)((long)in_sizes[4] / ((long)E * D)); // 4096
    const int  cap = (int)((long)N * 5 / (4 * E));   // 640
    const long ytot = (long)N * D;

    cudaFuncSetAttribute(gemm_kernel<0>, cudaFuncAttributeMaxDynamicSharedMemorySize, GSMEM);
    cudaFuncSetAttribute(gemm_kernel<1>, cudaFuncAttributeMaxDynamicSharedMemorySize, GSMEM);
    cudaFuncSetAttribute(rank_kernel, cudaFuncAttributeMaxDynamicSharedMemorySize, 65536);

    init_kernel<<<(unsigned)((ytot / 4 + 255) / 256), 256>>>(out, ytot);
    router_kernel<<<N / 8, 256>>>(x, mask, noise, Wr, N, D);
    loss_reduce_kernel<<<1, 32>>>(out, N / 8, (long)out_size);
    scan_kernel<<<N / 256, 256>>>(mask, N);
    rank_kernel<<<E, 256, (size_t)N * 8>>>(cap);

    ushort_t *xhi, *xlo;
    cudaGetSymbolAddress((void**)&xhi, g_xhi);
    cudaGetSymbolAddress((void**)&xlo, g_xlo);
    pack_kernel<<<2048, 256>>>(x, xhi, xlo, (long)N * D / 4);

    gemm_kernel<0><<<E * (H / 128) * 5, 256, GSMEM>>>(W1, out, cap);
    gemm_kernel<1><<<E * (D / 128) * 5, 256, GSMEM>>>(W2, out, cap);
}

// round 8
// speedup vs baseline: 1.2229x; 1.2229x over previous
#include <cuda_runtime.h>
#include <cstdint>
#include <cstddef>

typedef unsigned short ushort_t;

#define NTOK 8192
#define EEXP 16
#define CAPS 640
#define RBLKS (NTOK/8)

// ---------------- static device scratch ----------------
__device__ ushort_t g_xhi[(size_t)NTOK * 1024];
__device__ ushort_t g_xlo[(size_t)NTOK * 1024];
__device__ ushort_t g_w1hi[(size_t)EEXP * 1024 * 4096];
__device__ ushort_t g_w1lo[(size_t)EEXP * 1024 * 4096];
__device__ ushort_t g_w2hi[(size_t)EEXP * 4096 * 1024];
__device__ ushort_t g_w2lo[(size_t)EEXP * 4096 * 1024];
__device__ ushort_t g_hhi[(size_t)EEXP * CAPS * 4096];
__device__ ushort_t g_hlo[(size_t)EEXP * CAPS * 4096];
__device__ float g_gate[NTOK];
__device__ int   g_eid[NTOK];
__device__ int   g_cnt[EEXP];
__device__ int   g_lst_tok[EEXP * NTOK];
__device__ float g_lst_gate[EEXP * NTOK];
__device__ int   g_tok4slot[EEXP * CAPS];
__device__ float g_slotgate[EEXP * CAPS];
__device__ float g_pp[RBLKS * 16];
__device__ int   g_pf[RBLKS * 16];
__device__ float g_pz[RBLKS];
__device__ int   g_pn[RBLKS];

// ---------------- helpers ----------------
__device__ __forceinline__ uint32_t f2bf(float f) {
    uint32_t x = __float_as_uint(f);
    return (x + 0x7FFFu + ((x >> 16) & 1u)) >> 16;
}
__device__ __forceinline__ float bf2f(uint32_t b) { return __uint_as_float(b << 16); }
__device__ __forceinline__ uint32_t smem_u32(const void* p) {
    uint32_t a;
    asm("{ .reg .u64 t; cvta.to.shared.u64 t, %1; cvt.u32.u64 %0, t; }" : "=r"(a) : "l"(p));
    return a;
}
__device__ __forceinline__ void cpa16(uint32_t d, const void* s) {
    asm volatile("cp.async.cg.shared.global [%0], [%1], 16;" :: "r"(d), "l"(s));
}
__device__ __forceinline__ void cp_commit() { asm volatile("cp.async.commit_group;"); }
__device__ __forceinline__ void cp_wait0() { asm volatile("cp.async.wait_group 0;" ::: "memory"); }
__device__ __forceinline__ void cp_wait1() { asm volatile("cp.async.wait_group 1;" ::: "memory"); }
__device__ __forceinline__ void ldsm4(uint32_t* r, uint32_t a) {
    asm volatile("ldmatrix.sync.aligned.m8n8.x4.shared.b16 {%0,%1,%2,%3}, [%4];"
        : "=r"(r[0]), "=r"(r[1]), "=r"(r[2]), "=r"(r[3]) : "r"(a));
}
__device__ __forceinline__ void ldsm4t(uint32_t* r, uint32_t a) {
    asm volatile("ldmatrix.sync.aligned.m8n8.x4.trans.shared.b16 {%0,%1,%2,%3}, [%4];"
        : "=r"(r[0]), "=r"(r[1]), "=r"(r[2]), "=r"(r[3]) : "r"(a));
}
__device__ __forceinline__ void mma16816(float* c, const uint32_t* a, uint32_t b0, uint32_t b1) {
    asm volatile("mma.sync.aligned.m16n8k16.row.col.f32.bf16.bf16.f32 "
        "{%0,%1,%2,%3}, {%4,%5,%6,%7}, {%8,%9}, {%0,%1,%2,%3};"
        : "+f"(c[0]), "+f"(c[1]), "+f"(c[2]), "+f"(c[3])
        : "r"(a[0]), "r"(a[1]), "r"(a[2]), "r"(a[3]), "r"(b0), "r"(b1));
}

// ---------------- init: zero y + expert counters ----------------
__global__ void init_kernel(float* __restrict__ out, long ytot) {
    if (blockIdx.x == 0 && threadIdx.x < EEXP) g_cnt[threadIdx.x] = 0;
    long i4 = (long)blockIdx.x * blockDim.x + threadIdx.x;
    long n4 = ytot >> 2;
    long stride = (long)gridDim.x * blockDim.x;
    float4 z = make_float4(0.f, 0.f, 0.f, 0.f);
    for (; i4 < n4; i4 += stride) reinterpret_cast<float4*>(out)[i4] = z;
}

// ---------------- bf16 split pack ----------------
__global__ void pack_kernel(const float* __restrict__ in, ushort_t* __restrict__ hi,
                            ushort_t* __restrict__ lo, long n4)
{
    long i = (long)blockIdx.x * blockDim.x + threadIdx.x;
    long stride = (long)gridDim.x * blockDim.x;
    for (; i < n4; i += stride) {
        float4 v = reinterpret_cast<const float4*>(in)[i];
        uint32_t hx = f2bf(v.x), hy = f2bf(v.y), hz = f2bf(v.z), hw = f2bf(v.w);
        uint32_t lx = f2bf(v.x - bf2f(hx)), ly = f2bf(v.y - bf2f(hy));
        uint32_t lz = f2bf(v.z - bf2f(hz)), lw = f2bf(v.w - bf2f(hw));
        reinterpret_cast<uint2*>(hi)[i] = make_uint2(hx | (hy << 16), hz | (hw << 16));
        reinterpret_cast<uint2*>(lo)[i] = make_uint2(lx | (ly << 16), lz | (lw << 16));
    }
}

// ---------------- router ----------------
__global__ void __launch_bounds__(256) router_kernel(
    const float* __restrict__ x, const int* __restrict__ mask,
    const float* __restrict__ noise, const float* __restrict__ Wr, int N, int D)
{
    int warp = threadIdx.x >> 5, lane = threadIdx.x & 31;
    int t = blockIdx.x * 8 + warp;
    __shared__ float s_log[8][16];
    __shared__ float s_p[16]; __shared__ int s_f[16];
    __shared__ float s_z; __shared__ int s_n;
    if (threadIdx.x < 16) { s_p[threadIdx.x] = 0.f; s_f[threadIdx.x] = 0; }
    if (threadIdx.x == 0) { s_z = 0.f; s_n = 0; }
    __syncthreads();
    if (t < N) {
        float acc[16];
#pragma unroll
        for (int e = 0; e < 16; ++e) acc[e] = 0.f;
        const float* xr = x + (size_t)t * D;
        for (int d = lane; d < D; d += 32) {
            float xv = xr[d];
            const float* w = Wr + (size_t)d * 16;
#pragma unroll
            for (int e = 0; e < 16; ++e) acc[e] = fmaf(xv, w[e], acc[e]);
        }
#pragma unroll
        for (int e = 0; e < 16; ++e) {
            float v = acc[e];
#pragma unroll
            for (int o = 16; o; o >>= 1) v += __shfl_xor_sync(0xFFFFFFFFu, v, o);
            if (lane == 0) s_log[warp][e] = v;
        }
        __syncwarp();
        int e = lane & 15;
        float lc = s_log[warp][e];
        int mk = mask[t] ? 1 : 0;
        float nz = noise[(size_t)t * 16 + e];
        float mult = mk ? (1.0f + (nz * 2.0f - 1.0f) * 0.1f) : 1.0f;
        float ln = lc * mult;
        float mx = ln;
#pragma unroll
        for (int o = 8; o; o >>= 1) mx = fmaxf(mx, __shfl_xor_sync(0xFFFFFFFFu, mx, o, 16));
        unsigned bal = __ballot_sync(0xFFFFFFFFu, ln == mx);
        int eid = __ffs(bal) - 1;
        float se = expf(ln - mx);
#pragma unroll
        for (int o = 8; o; o >>= 1) se += __shfl_xor_sync(0xFFFFFFFFu, se, o, 16);
        float lse = mx + logf(se);
        float gate = expf(mx - lse);
        float mxc = lc;
#pragma unroll
        for (int o = 8; o; o >>= 1) mxc = fmaxf(mxc, __shfl_xor_sync(0xFFFFFFFFu, mxc, o, 16));
        unsigned balc = __ballot_sync(0xFFFFFFFFu, lc == mxc);
        int eidc = __ffs(balc) - 1;
        float sec = expf(lc - mxc);
#pragma unroll
        for (int o = 8; o; o >>= 1) sec += __shfl_xor_sync(0xFFFFFFFFu, sec, o, 16);
        float lsec = mxc + logf(sec);
        float pce = expf(lc - lsec);
        if (lane < 16 && mk) {
            atomicAdd(&s_p[e], pce);
            if (e == eidc) atomicAdd(&s_f[e], 1);
        }
        if (lane == 0) {
            g_gate[t] = gate; g_eid[t] = eid;
            if (mk) { atomicAdd(&s_z, lsec * lsec); atomicAdd(&s_n, 1); }
        }
    }
    __syncthreads();
    if (threadIdx.x < 16) {
        g_pp[blockIdx.x * 16 + threadIdx.x] = s_p[threadIdx.x];
        g_pf[blockIdx.x * 16 + threadIdx.x] = s_f[threadIdx.x];
    }
    if (threadIdx.x == 0) { g_pz[blockIdx.x] = s_z; g_pn[blockIdx.x] = s_n; }
}

__global__ void loss_reduce_kernel(float* __restrict__ out, int nb, long outsz) {
    __shared__ float sp[16], sf[16], szn[2];
    int tid = threadIdx.x;
    if (tid < 16) {
        float s = 0.f; int c = 0;
        for (int b = 0; b < nb; ++b) { s += g_pp[b * 16 + tid]; c += g_pf[b * 16 + tid]; }
        sp[tid] = s; sf[tid] = (float)c;
    }
    if (tid == 16) { float s = 0.f; for (int b = 0; b < nb; ++b) s += g_pz[b]; szn[0] = s; }
    if (tid == 17) { int c = 0; for (int b = 0; b < nb; ++b) c += g_pn[b]; szn[1] = (float)c; }
    __syncthreads();
    if (tid == 0) {
        float n = szn[1], lb = 0.f;
        for (int e = 0; e < 16; ++e) lb += (sp[e] / n) * (sf[e] / n);
        out[outsz - 2] = lb * 16.0f;
        out[outsz - 1] = szn[0] / n;
    }
}

// ---------------- dispatch: parallel scan + per-expert rank ----------------
__global__ void __launch_bounds__(256) scan_kernel(const int* __restrict__ mask, int N)
{
    int t = blockIdx.x * blockDim.x + threadIdx.x;
    if (t < N && mask[t]) {
        int e = g_eid[t];
        int i = atomicAdd(&g_cnt[e], 1);
        g_lst_tok[e * NTOK + i] = t;
        g_lst_gate[e * NTOK + i] = g_gate[t];
    }
}

__global__ void __launch_bounds__(256) rank_kernel(int cap)
{
    extern __shared__ char dsm[];
    float* sg = (float*)dsm;
    int*   st = (int*)(dsm + (size_t)NTOK * 4);
    int e = blockIdx.x, tid = threadIdx.x;
    for (int i = tid; i < cap; i += 256) {
        g_tok4slot[e * cap + i] = -1;
        g_slotgate[e * cap + i] = 0.f;
    }
    int cnt = g_cnt[e];
    for (int i = tid; i < cnt; i += 256) {
        st[i] = g_lst_tok[e * NTOK + i];
        sg[i] = g_lst_gate[e * NTOK + i];
    }
    __syncthreads();
    for (int i = tid; i < cnt; i += 256) {
        int ti = st[i]; float gi = sg[i];
        int r = 0;
        for (int j = 0; j < cnt; ++j) {
            float gj = sg[j]; int tj = st[j];
            r += (gj > gi) || (gj == gi && tj < ti);
        }
        if (r < cap) {
            g_tok4slot[e * cap + r] = ti;
            g_slotgate[e * cap + r] = gi;
        }
    }
}

// ---------------- bf16-split tensor-core GEMM, 3-stage cp.async pipeline ----
// CTA tile 128m x 128n, BK=32, 8 warps (4m x 2n), warp tile 32x64.
// 3 SMEM stages, prefetch depth 2, ONE __syncthreads per chunk.
// MODE 0: h = relu(gather(x) @ W1[e]); MODE 1: y = (h @ W2[e]) * gate
#define STG 36864
#define ABUF(s, p) ((s) * STG + (p) * 10240)
#define BBUF(s, p) ((s) * STG + 20480 + (p) * 8192)
#define GSMEM (3 * STG)

template<int MODE>
__global__ void __launch_bounds__(256, 2) gemm_kernel(
    const float* __restrict__ xunused, float* __restrict__ y, int cap)
{
    const int K   = (MODE == 0) ? 1024 : 4096;
    const int NT  = (MODE == 0) ? 32 : 8;
    const int Nn  = (MODE == 0) ? 4096 : 1024;
    const int NCH = K / 32;

    int b = blockIdx.x;
    const int m  = b % 5; b /= 5;
    const int n  = b % NT;
    const int e  = b / NT;
    const int m0 = m * 128, n0 = n * 128;

    extern __shared__ char smem[];
    const uint32_t sb = smem_u32(smem);
    __shared__ int s_arow[128];

    const int tid = threadIdx.x, wid = tid >> 5, lane = tid & 31;
    const int wm = wid & 3, wn = wid >> 2;

    if (tid < 128) {
        if (MODE == 0) {
            int tok = g_tok4slot[e * cap + m0 + tid];
            s_arow[tid] = (tok >= 0) ? tok : 0;
        } else {
            s_arow[tid] = e * CAPS + m0 + tid;
        }
    }
    __syncthreads();

    const ushort_t* AHI = (MODE == 0) ? g_xhi : g_hhi;
    const ushort_t* ALO = (MODE == 0) ? g_xlo : g_hlo;
    const ushort_t* BHI = ((MODE == 0) ? g_w1hi : g_w2hi) + (size_t)e * K * Nn;
    const ushort_t* BLO = ((MODE == 0) ? g_w1lo : g_w2lo) + (size_t)e * K * Nn;

    // per-thread fixed load coordinates
    const int ar0 = tid >> 2, ac0 = tid & 3;
    const int ar1 = (tid + 256) >> 2;
    const int bk0 = tid >> 4, bc0 = tid & 15;
    const int bk1 = (tid + 256) >> 4, bc1 = tid & 15;
    const ushort_t* aHi0 = AHI + (size_t)s_arow[ar0] * K + ac0 * 8;
    const ushort_t* aLo0 = ALO + (size_t)s_arow[ar0] * K + ac0 * 8;
    const ushort_t* aHi1 = AHI + (size_t)s_arow[ar1] * K + ac0 * 8;
    const ushort_t* aLo1 = ALO + (size_t)s_arow[ar1] * K + ac0 * 8;
    const ushort_t* bHi0 = BHI + (size_t)bk0 * Nn + n0 + bc0 * 8;
    const ushort_t* bLo0 = BLO + (size_t)bk0 * Nn + n0 + bc0 * 8;
    const ushort_t* bHi1 = BHI + (size_t)bk1 * Nn + n0 + bc1 * 8;
    const ushort_t* bLo1 = BLO + (size_t)bk1 * Nn + n0 + bc1 * 8;
    const uint32_t aoff0 = ar0 * 80 + ac0 * 16, aoff1 = ar1 * 80 + ac0 * 16;
    const uint32_t boff0 = bk0 * 256 + ((bc0 ^ (bk0 & 7)) << 4);
    const uint32_t boff1 = bk1 * 256 + ((bc1 ^ (bk1 & 7)) << 4);

    float acc[2][8][4];
#pragma unroll
    for (int i = 0; i < 2; ++i)
#pragma unroll
        for (int j = 0; j < 8; ++j)
#pragma unroll
            for (int q = 0; q < 4; ++q) acc[i][j][q] = 0.f;

    auto issue = [&](int kt, int s) {
        const long ka = (long)kt * 32;
        cpa16(sb + ABUF(s, 0) + aoff0, aHi0 + ka);
        cpa16(sb + ABUF(s, 0) + aoff1, aHi1 + ka);
        cpa16(sb + ABUF(s, 1) + aoff0, aLo0 + ka);
        cpa16(sb + ABUF(s, 1) + aoff1, aLo1 + ka);
        const long kb = (long)kt * 32 * Nn;
        cpa16(sb + BBUF(s, 0) + boff0, bHi0 + kb);
        cpa16(sb + BBUF(s, 0) + boff1, bHi1 + kb);
        cpa16(sb + BBUF(s, 1) + boff0, bLo0 + kb);
        cpa16(sb + BBUF(s, 1) + boff1, bLo1 + kb);
        cp_commit();
    };

    issue(0, 0);
    issue(1, 1);

    const uint32_t a_row = (lane & 15), a_kq = (lane >> 4);
    const uint32_t b_kr = (lane & 7) + (lane >> 4) * 8;
    const uint32_t b_nc = wn * 8 + ((lane >> 3) & 1);

    int s = 0;
    for (int kt = 0; kt < NCH; ++kt) {
        if (kt + 1 < NCH) cp_wait1(); else cp_wait0();
        __syncthreads();   // data visible to all; all warps done with stage (kt+2)%3
        if (kt + 2 < NCH) issue(kt + 2, (s + 2 >= 3) ? s - 1 : s + 2);

        const uint32_t aH = sb + ABUF(s, 0), aL = sb + ABUF(s, 1);
        const uint32_t bH = sb + BBUF(s, 0), bL = sb + BBUF(s, 1);

#pragma unroll
        for (int ks = 0; ks < 2; ++ks) {
            uint32_t fAH[2][4], fAL[2][4];
#pragma unroll
            for (int tm = 0; tm < 2; ++tm) {
                uint32_t ao = (wm * 32 + tm * 16 + a_row) * 80 + (ks * 16 + a_kq * 8) * 2;
                ldsm4(fAH[tm], aH + ao);
                ldsm4(fAL[tm], aL + ao);
            }
            const uint32_t kr = ks * 16 + b_kr;
            const uint32_t krl = kr & 7;
#pragma unroll
            for (int nb = 0; nb < 4; ++nb) {
                uint32_t nc = b_nc + nb * 2;
                uint32_t bo = kr * 256 + ((nc ^ krl) << 4);
                uint32_t fBH[4], fBL[4];
                ldsm4t(fBH, bH + bo);
                ldsm4t(fBL, bL + bo);
#pragma unroll
                for (int tm = 0; tm < 2; ++tm) {
                    mma16816(acc[tm][nb * 2 + 0], fAH[tm], fBH[0], fBH[2]);
                    mma16816(acc[tm][nb * 2 + 1], fAH[tm], fBH[1], fBH[3]);
                    mma16816(acc[tm][nb * 2 + 0], fAH[tm], fBL[0], fBL[2]);
                    mma16816(acc[tm][nb * 2 + 1], fAH[tm], fBL[1], fBL[3]);
                    mma16816(acc[tm][nb * 2 + 0], fAL[tm], fBH[0], fBH[2]);
                    mma16816(acc[tm][nb * 2 + 1], fAL[tm], fBH[1], fBH[3]);
                }
            }
        }
        s = (s + 1 >= 3) ? 0 : s + 1;
    }

    // ---- epilogue ----
    const int gid = lane >> 2, tig = lane & 3;
#pragma unroll
    for (int tm = 0; tm < 2; ++tm) {
        const int r0 = m0 + wm * 32 + tm * 16 + gid;
#pragma unroll
        for (int j = 0; j < 8; ++j) {
            const int col = n0 + wn * 64 + j * 8 + tig * 2;
            if (MODE == 0) {
#pragma unroll
                for (int hh = 0; hh < 2; ++hh) {
                    int row = r0 + hh * 8;
                    float v0 = fmaxf(acc[tm][j][hh * 2 + 0], 0.f);
                    float v1 = fmaxf(acc[tm][j][hh * 2 + 1], 0.f);
                    uint32_t h0 = f2bf(v0), h1 = f2bf(v1);
                    uint32_t l0 = f2bf(v0 - bf2f(h0)), l1 = f2bf(v1 - bf2f(h1));
                    size_t idx = (size_t)(e * CAPS + row) * 4096 + col;
                    *(uint32_t*)(g_hhi + idx) = h0 | (h1 << 16);
                    *(uint32_t*)(g_hlo + idx) = l0 | (l1 << 16);
                }
            } else {
#pragma unroll
                for (int hh = 0; hh < 2; ++hh) {
                    int row = r0 + hh * 8;
                    int slot = e * cap + row;
                    int tok = g_tok4slot[slot];
                    if (tok >= 0) {
                        float g = g_slotgate[slot];
                        float2 v;
                        v.x = acc[tm][j][hh * 2 + 0] * g;
                        v.y = acc[tm][j][hh * 2 + 1] * g;
                        *(float2*)(y + (size_t)tok * 1024 + col) = v;
                    }
                }
            }
        }
    }
}

// ---------------- launch ----------------
extern "C" void kernel_launch(void* const* d_in, const int* in_sizes, int n_in,
                              void* d_out, int out_size)
{
    const float* x     = (const float*)d_in[0];
    const int*   mask  = (const int*)d_in[1];
    const float* noise = (const float*)d_in[2];
    const float* Wr    = (const float*)d_in[3];
    const float* W1    = (const float*)d_in[4];
    const float* W2    = (const float*)d_in[5];
    float*       out   = (float*)d_out;

    const int  N = in_sizes[1];                      // 8192
    const int  D = in_sizes[0] / N;                  // 1024
    const int  E = in_sizes[2] / N;                  // 16
    const int  H = (int)((long)in_sizes[4] / ((long)E * D)); // 4096
    const int  cap = (int)((long)N * 5 / (4 * E));   // 640
    const long ytot = (long)N * D;

    cudaFuncSetAttribute(gemm_kernel<0>, cudaFuncAttributeMaxDynamicSharedMemorySize, GSMEM);
    cudaFuncSetAttribute(gemm_kernel<1>, cudaFuncAttributeMaxDynamicSharedMemorySize, GSMEM);
    cudaFuncSetAttribute(rank_kernel, cudaFuncAttributeMaxDynamicSharedMemorySize, 65536);

    init_kernel<<<(unsigned)((ytot / 4 + 255) / 256), 256>>>(out, ytot);
    router_kernel<<<N / 8, 256>>>(x, mask, noise, Wr, N, D);
    loss_reduce_kernel<<<1, 32>>>(out, N / 8, (long)out_size);
    scan_kernel<<<N / 256, 256>>>(mask, N);
    rank_kernel<<<E, 256, (size_t)N * 8>>>(cap);

    ushort_t *xhi, *xlo, *w1hi, *w1lo, *w2hi, *w2lo;
    cudaGetSymbolAddress((void**)&xhi, g_xhi);
    cudaGetSymbolAddress((void**)&xlo, g_xlo);
    cudaGetSymbolAddress((void**)&w1hi, g_w1hi);
    cudaGetSymbolAddress((void**)&w1lo, g_w1lo);
    cudaGetSymbolAddress((void**)&w2hi, g_w2hi);
    cudaGetSymbolAddress((void**)&w2lo, g_w2lo);

    pack_kernel<<<2048, 256>>>(x, xhi, xlo, (long)N * D / 4);
    pack_kernel<<<4096, 256>>>(W1, w1hi, w1lo, (long)E * D * H / 4);
    pack_kernel<<<4096, 256>>>(W2, w2hi, w2lo, (long)E * D * H / 4);

    gemm_kernel<0><<<E * (H / 128) * 5, 256, GSMEM>>>(x, out, cap);
    gemm_kernel<1><<<E * (D / 128) * 5, 256, GSMEM>>>(x, out, cap);
}

// round 9
// speedup vs baseline: 1.5195x; 1.2426x over previous
#include <cuda_runtime.h>
#include <cuda_fp16.h>
#include <cstdint>
#include <cstddef>

typedef unsigned short ushort_t;

#define NTOK 8192
#define EEXP 16
#define CAPS 640
#define RBLKS (NTOK/8)

// ---------------- static device scratch ----------------
__device__ ushort_t g_xhi[(size_t)NTOK * 1024];
__device__ ushort_t g_xlo[(size_t)NTOK * 1024];
__device__ ushort_t g_w1h[(size_t)EEXP * 1024 * 4096];
__device__ ushort_t g_w2h[(size_t)EEXP * 4096 * 1024];
__device__ ushort_t g_hhi[(size_t)EEXP * CAPS * 4096];
__device__ ushort_t g_hlo[(size_t)EEXP * CAPS * 4096];
__device__ float g_gate[NTOK];
__device__ int   g_eid[NTOK];
__device__ int   g_cnt[EEXP];
__device__ int   g_lst_tok[EEXP * NTOK];
__device__ float g_lst_gate[EEXP * NTOK];
__device__ int   g_tok4slot[EEXP * CAPS];
__device__ float g_slotgate[EEXP * CAPS];
__device__ float g_pp[RBLKS * 16];
__device__ int   g_pf[RBLKS * 16];
__device__ float g_pz[RBLKS];
__device__ int   g_pn[RBLKS];

// ---------------- helpers ----------------
__device__ __forceinline__ uint32_t f2h(float f) {
    return (uint32_t)__half_as_ushort(__float2half_rn(f));
}
__device__ __forceinline__ float h2f(uint32_t h) {
    return __half2float(__ushort_as_half((ushort_t)h));
}
__device__ __forceinline__ uint32_t smem_u32(const void* p) {
    uint32_t a;
    asm("{ .reg .u64 t; cvta.to.shared.u64 t, %1; cvt.u32.u64 %0, t; }" : "=r"(a) : "l"(p));
    return a;
}
__device__ __forceinline__ void cpa16(uint32_t d, const void* s) {
    asm volatile("cp.async.cg.shared.global [%0], [%1], 16;" :: "r"(d), "l"(s));
}
__device__ __forceinline__ void cp_commit() { asm volatile("cp.async.commit_group;"); }
__device__ __forceinline__ void cp_wait0() { asm volatile("cp.async.wait_group 0;" ::: "memory"); }
__device__ __forceinline__ void cp_wait1() { asm volatile("cp.async.wait_group 1;" ::: "memory"); }
__device__ __forceinline__ void ldsm4(uint32_t* r, uint32_t a) {
    asm volatile("ldmatrix.sync.aligned.m8n8.x4.shared.b16 {%0,%1,%2,%3}, [%4];"
        : "=r"(r[0]), "=r"(r[1]), "=r"(r[2]), "=r"(r[3]) : "r"(a));
}
__device__ __forceinline__ void ldsm4t(uint32_t* r, uint32_t a) {
    asm volatile("ldmatrix.sync.aligned.m8n8.x4.trans.shared.b16 {%0,%1,%2,%3}, [%4];"
        : "=r"(r[0]), "=r"(r[1]), "=r"(r[2]), "=r"(r[3]) : "r"(a));
}
__device__ __forceinline__ void mmaf16(float* c, const uint32_t* a, uint32_t b0, uint32_t b1) {
    asm volatile("mma.sync.aligned.m16n8k16.row.col.f32.f16.f16.f32 "
        "{%0,%1,%2,%3}, {%4,%5,%6,%7}, {%8,%9}, {%0,%1,%2,%3};"
        : "+f"(c[0]), "+f"(c[1]), "+f"(c[2]), "+f"(c[3])
        : "r"(a[0]), "r"(a[1]), "r"(a[2]), "r"(a[3]), "r"(b0), "r"(b1));
}

// ---------------- init: zero y + expert counters ----------------
__global__ void init_kernel(float* __restrict__ out, long ytot) {
    if (blockIdx.x == 0 && threadIdx.x < EEXP) g_cnt[threadIdx.x] = 0;
    long i4 = (long)blockIdx.x * blockDim.x + threadIdx.x;
    long n4 = ytot >> 2;
    long stride = (long)gridDim.x * blockDim.x;
    float4 z = make_float4(0.f, 0.f, 0.f, 0.f);
    for (; i4 < n4; i4 += stride) reinterpret_cast<float4*>(out)[i4] = z;
}

// ---------------- fp16 split pack (x, 2-term) ----------------
__global__ void pack_split_kernel(const float* __restrict__ in, ushort_t* __restrict__ hi,
                                  ushort_t* __restrict__ lo, long n4)
{
    long i = (long)blockIdx.x * blockDim.x + threadIdx.x;
    long stride = (long)gridDim.x * blockDim.x;
    for (; i < n4; i += stride) {
        float4 v = reinterpret_cast<const float4*>(in)[i];
        uint32_t hx = f2h(v.x), hy = f2h(v.y), hz = f2h(v.z), hw = f2h(v.w);
        uint32_t lx = f2h(v.x - h2f(hx)), ly = f2h(v.y - h2f(hy));
        uint32_t lz = f2h(v.z - h2f(hz)), lw = f2h(v.w - h2f(hw));
        reinterpret_cast<uint2*>(hi)[i] = make_uint2(hx | (hy << 16), hz | (hw << 16));
        reinterpret_cast<uint2*>(lo)[i] = make_uint2(lx | (ly << 16), lz | (lw << 16));
    }
}

// ---------------- fp16 single pack (weights) ----------------
__global__ void pack_single_kernel(const float* __restrict__ in, ushort_t* __restrict__ h,
                                   long n4)
{
    long i = (long)blockIdx.x * blockDim.x + threadIdx.x;
    long stride = (long)gridDim.x * blockDim.x;
    for (; i < n4; i += stride) {
        float4 v = reinterpret_cast<const float4*>(in)[i];
        uint32_t hx = f2h(v.x), hy = f2h(v.y), hz = f2h(v.z), hw = f2h(v.w);
        reinterpret_cast<uint2*>(h)[i] = make_uint2(hx | (hy << 16), hz | (hw << 16));
    }
}

// ---------------- router ----------------
__global__ void __launch_bounds__(256) router_kernel(
    const float* __restrict__ x, const int* __restrict__ mask,
    const float* __restrict__ noise, const float* __restrict__ Wr, int N, int D)
{
    int warp = threadIdx.x >> 5, lane = threadIdx.x & 31;
    int t = blockIdx.x * 8 + warp;
    __shared__ float s_log[8][16];
    __shared__ float s_p[16]; __shared__ int s_f[16];
    __shared__ float s_z; __shared__ int s_n;
    if (threadIdx.x < 16) { s_p[threadIdx.x] = 0.f; s_f[threadIdx.x] = 0; }
    if (threadIdx.x == 0) { s_z = 0.f; s_n = 0; }
    __syncthreads();
    if (t < N) {
        float acc[16];
#pragma unroll
        for (int e = 0; e < 16; ++e) acc[e] = 0.f;
        const float* xr = x + (size_t)t * D;
        for (int d = lane; d < D; d += 32) {
            float xv = xr[d];
            const float* w = Wr + (size_t)d * 16;
#pragma unroll
            for (int e = 0; e < 16; ++e) acc[e] = fmaf(xv, w[e], acc[e]);
        }
#pragma unroll
        for (int e = 0; e < 16; ++e) {
            float v = acc[e];
#pragma unroll
            for (int o = 16; o; o >>= 1) v += __shfl_xor_sync(0xFFFFFFFFu, v, o);
            if (lane == 0) s_log[warp][e] = v;
        }
        __syncwarp();
        int e = lane & 15;
        float lc = s_log[warp][e];
        int mk = mask[t] ? 1 : 0;
        float nz = noise[(size_t)t * 16 + e];
        float mult = mk ? (1.0f + (nz * 2.0f - 1.0f) * 0.1f) : 1.0f;
        float ln = lc * mult;
        float mx = ln;
#pragma unroll
        for (int o = 8; o; o >>= 1) mx = fmaxf(mx, __shfl_xor_sync(0xFFFFFFFFu, mx, o, 16));
        unsigned bal = __ballot_sync(0xFFFFFFFFu, ln == mx);
        int eid = __ffs(bal) - 1;
        float se = expf(ln - mx);
#pragma unroll
        for (int o = 8; o; o >>= 1) se += __shfl_xor_sync(0xFFFFFFFFu, se, o, 16);
        float lse = mx + logf(se);
        float gate = expf(mx - lse);
        float mxc = lc;
#pragma unroll
        for (int o = 8; o; o >>= 1) mxc = fmaxf(mxc, __shfl_xor_sync(0xFFFFFFFFu, mxc, o, 16));
        unsigned balc = __ballot_sync(0xFFFFFFFFu, lc == mxc);
        int eidc = __ffs(balc) - 1;
        float sec = expf(lc - mxc);
#pragma unroll
        for (int o = 8; o; o >>= 1) sec += __shfl_xor_sync(0xFFFFFFFFu, sec, o, 16);
        float lsec = mxc + logf(sec);
        float pce = expf(lc - lsec);
        if (lane < 16 && mk) {
            atomicAdd(&s_p[e], pce);
            if (e == eidc) atomicAdd(&s_f[e], 1);
        }
        if (lane == 0) {
            g_gate[t] = gate; g_eid[t] = eid;
            if (mk) { atomicAdd(&s_z, lsec * lsec); atomicAdd(&s_n, 1); }
        }
    }
    __syncthreads();
    if (threadIdx.x < 16) {
        g_pp[blockIdx.x * 16 + threadIdx.x] = s_p[threadIdx.x];
        g_pf[blockIdx.x * 16 + threadIdx.x] = s_f[threadIdx.x];
    }
    if (threadIdx.x == 0) { g_pz[blockIdx.x] = s_z; g_pn[blockIdx.x] = s_n; }
}

__global__ void loss_reduce_kernel(float* __restrict__ out, int nb, long outsz) {
    __shared__ float sp[16], sf[16], szn[2];
    int tid = threadIdx.x;
    if (tid < 16) {
        float s = 0.f; int c = 0;
        for (int b = 0; b < nb; ++b) { s += g_pp[b * 16 + tid]; c += g_pf[b * 16 + tid]; }
        sp[tid] = s; sf[tid] = (float)c;
    }
    if (tid == 16) { float s = 0.f; for (int b = 0; b < nb; ++b) s += g_pz[b]; szn[0] = s; }
    if (tid == 17) { int c = 0; for (int b = 0; b < nb; ++b) c += g_pn[b]; szn[1] = (float)c; }
    __syncthreads();
    if (tid == 0) {
        float n = szn[1], lb = 0.f;
        for (int e = 0; e < 16; ++e) lb += (sp[e] / n) * (sf[e] / n);
        out[outsz - 2] = lb * 16.0f;
        out[outsz - 1] = szn[0] / n;
    }
}

// ---------------- dispatch: parallel scan + per-expert rank ----------------
__global__ void __launch_bounds__(256) scan_kernel(const int* __restrict__ mask, int N)
{
    int t = blockIdx.x * blockDim.x + threadIdx.x;
    if (t < N && mask[t]) {
        int e = g_eid[t];
        int i = atomicAdd(&g_cnt[e], 1);
        g_lst_tok[e * NTOK + i] = t;
        g_lst_gate[e * NTOK + i] = g_gate[t];
    }
}

__global__ void __launch_bounds__(256) rank_kernel(int cap)
{
    extern __shared__ char dsm[];
    float* sg = (float*)dsm;
    int*   st = (int*)(dsm + (size_t)NTOK * 4);
    int e = blockIdx.x, tid = threadIdx.x;
    for (int i = tid; i < cap; i += 256) {
        g_tok4slot[e * cap + i] = -1;
        g_slotgate[e * cap + i] = 0.f;
    }
    int cnt = g_cnt[e];
    for (int i = tid; i < cnt; i += 256) {
        st[i] = g_lst_tok[e * NTOK + i];
        sg[i] = g_lst_gate[e * NTOK + i];
    }
    __syncthreads();
    for (int i = tid; i < cnt; i += 256) {
        int ti = st[i]; float gi = sg[i];
        int r = 0;
        for (int j = 0; j < cnt; ++j) {
            float gj = sg[j]; int tj = st[j];
            r += (gj > gi) || (gj == gi && tj < ti);
        }
        if (r < cap) {
            g_tok4slot[e * cap + r] = ti;
            g_slotgate[e * cap + r] = gi;
        }
    }
}

// ---------------- fp16 2-pass tensor-core GEMM (A split hi/lo, B single) ----
// CTA tile 128m x 128n, BK=32, 8 warps (4m x 2n), warp tile 32x64.
// 2 passes per chunk: aHi*b + aLo*b into fp32 acc. 2-stage cp.async pipeline.
// MODE 0: h = relu(gather(x) @ W1[e]); MODE 1: y = (h @ W2[e]) * gate
#define STG 28672
#define ABUF(s, p) ((s) * STG + (p) * 10240)
#define BBUF(s)    ((s) * STG + 20480)
#define GSMEM (2 * STG)

template<int MODE>
__global__ void __launch_bounds__(256, 2) gemm_kernel(
    const float* __restrict__ xunused, float* __restrict__ y, int cap)
{
    const int K   = (MODE == 0) ? 1024 : 4096;
    const int NT  = (MODE == 0) ? 32 : 8;
    const int Nn  = (MODE == 0) ? 4096 : 1024;
    const int NCH = K / 32;

    int b = blockIdx.x;
    const int m  = b % 5; b /= 5;
    const int n  = b % NT;
    const int e  = b / NT;
    const int m0 = m * 128, n0 = n * 128;

    extern __shared__ char smem[];
    const uint32_t sb = smem_u32(smem);
    __shared__ int s_arow[128];

    const int tid = threadIdx.x, wid = tid >> 5, lane = tid & 31;
    const int wm = wid & 3, wn = wid >> 2;

    if (tid < 128) {
        if (MODE == 0) {
            int tok = g_tok4slot[e * cap + m0 + tid];
            s_arow[tid] = (tok >= 0) ? tok : 0;
        } else {
            s_arow[tid] = e * CAPS + m0 + tid;
        }
    }
    __syncthreads();

    const ushort_t* AHI = (MODE == 0) ? g_xhi : g_hhi;
    const ushort_t* ALO = (MODE == 0) ? g_xlo : g_hlo;
    const ushort_t* BH  = ((MODE == 0) ? g_w1h : g_w2h) + (size_t)e * K * Nn;

    // per-thread fixed load coordinates
    const int ar0 = tid >> 2, ac0 = tid & 3;
    const int ar1 = (tid + 256) >> 2;
    const int bk0 = tid >> 4, bc0 = tid & 15;
    const int bk1 = (tid + 256) >> 4, bc1 = tid & 15;
    const ushort_t* aHi0 = AHI + (size_t)s_arow[ar0] * K + ac0 * 8;
    const ushort_t* aLo0 = ALO + (size_t)s_arow[ar0] * K + ac0 * 8;
    const ushort_t* aHi1 = AHI + (size_t)s_arow[ar1] * K + ac0 * 8;
    const ushort_t* aLo1 = ALO + (size_t)s_arow[ar1] * K + ac0 * 8;
    const ushort_t* bH0 = BH + (size_t)bk0 * Nn + n0 + bc0 * 8;
    const ushort_t* bH1 = BH + (size_t)bk1 * Nn + n0 + bc1 * 8;
    const uint32_t aoff0 = ar0 * 80 + ac0 * 16, aoff1 = ar1 * 80 + ac0 * 16;
    const uint32_t boff0 = bk0 * 256 + ((bc0 ^ (bk0 & 7)) << 4);
    const uint32_t boff1 = bk1 * 256 + ((bc1 ^ (bk1 & 7)) << 4);

    float acc[2][8][4];
#pragma unroll
    for (int i = 0; i < 2; ++i)
#pragma unroll
        for (int j = 0; j < 8; ++j)
#pragma unroll
            for (int q = 0; q < 4; ++q) acc[i][j][q] = 0.f;

    auto issue = [&](int kt, int buf) {
        const long ka = (long)kt * 32;
        cpa16(sb + ABUF(buf, 0) + aoff0, aHi0 + ka);
        cpa16(sb + ABUF(buf, 0) + aoff1, aHi1 + ka);
        cpa16(sb + ABUF(buf, 1) + aoff0, aLo0 + ka);
        cpa16(sb + ABUF(buf, 1) + aoff1, aLo1 + ka);
        const long kb = (long)kt * 32 * Nn;
        cpa16(sb + BBUF(buf) + boff0, bH0 + kb);
        cpa16(sb + BBUF(buf) + boff1, bH1 + kb);
        cp_commit();
    };

    issue(0, 0);

    const uint32_t a_row = (lane & 15), a_kq = (lane >> 4);
    const uint32_t b_kr = (lane & 7) + (lane >> 4) * 8;
    const uint32_t b_nc = wn * 8 + ((lane >> 3) & 1);

    for (int kt = 0; kt < NCH; ++kt) {
        const int buf = kt & 1;
        if (kt + 1 < NCH) { issue(kt + 1, buf ^ 1); cp_wait1(); }
        else cp_wait0();
        __syncthreads();

        const uint32_t aH = sb + ABUF(buf, 0), aL = sb + ABUF(buf, 1);
        const uint32_t bB = sb + BBUF(buf);

#pragma unroll
        for (int ks = 0; ks < 2; ++ks) {
            uint32_t fAH[2][4], fAL[2][4];
#pragma unroll
            for (int tm = 0; tm < 2; ++tm) {
                uint32_t ao = (wm * 32 + tm * 16 + a_row) * 80 + (ks * 16 + a_kq * 8) * 2;
                ldsm4(fAH[tm], aH + ao);
                ldsm4(fAL[tm], aL + ao);
            }
            const uint32_t kr = ks * 16 + b_kr;
            const uint32_t krl = kr & 7;
#pragma unroll
            for (int nb = 0; nb < 4; ++nb) {
                uint32_t nc = b_nc + nb * 2;
                uint32_t bo = kr * 256 + ((nc ^ krl) << 4);
                uint32_t fB[4];
                ldsm4t(fB, bB + bo);
#pragma unroll
                for (int tm = 0; tm < 2; ++tm) {
                    mmaf16(acc[tm][nb * 2 + 0], fAH[tm], fB[0], fB[2]);
                    mmaf16(acc[tm][nb * 2 + 1], fAH[tm], fB[1], fB[3]);
                    mmaf16(acc[tm][nb * 2 + 0], fAL[tm], fB[0], fB[2]);
                    mmaf16(acc[tm][nb * 2 + 1], fAL[tm], fB[1], fB[3]);
                }
            }
        }
        __syncthreads();
    }

    // ---- epilogue ----
    const int gid = lane >> 2, tig = lane & 3;
#pragma unroll
    for (int tm = 0; tm < 2; ++tm) {
        const int r0 = m0 + wm * 32 + tm * 16 + gid;
#pragma unroll
        for (int j = 0; j < 8; ++j) {
            const int col = n0 + wn * 64 + j * 8 + tig * 2;
            if (MODE == 0) {
#pragma unroll
                for (int hh = 0; hh < 2; ++hh) {
                    int row = r0 + hh * 8;
                    float v0 = fmaxf(acc[tm][j][hh * 2 + 0], 0.f);
                    float v1 = fmaxf(acc[tm][j][hh * 2 + 1], 0.f);
                    uint32_t h0 = f2h(v0), h1 = f2h(v1);
                    uint32_t l0 = f2h(v0 - h2f(h0)), l1 = f2h(v1 - h2f(h1));
                    size_t idx = (size_t)(e * CAPS + row) * 4096 + col;
                    *(uint32_t*)(g_hhi + idx) = h0 | (h1 << 16);
                    *(uint32_t*)(g_hlo + idx) = l0 | (l1 << 16);
                }
            } else {
#pragma unroll
                for (int hh = 0; hh < 2; ++hh) {
                    int row = r0 + hh * 8;
                    int slot = e * cap + row;
                    int tok = g_tok4slot[slot];
                    if (tok >= 0) {
                        float g = g_slotgate[slot];
                        float2 v;
                        v.x = acc[tm][j][hh * 2 + 0] * g;
                        v.y = acc[tm][j][hh * 2 + 1] * g;
                        *(float2*)(y + (size_t)tok * 1024 + col) = v;
                    }
                }
            }
        }
    }
}

// ---------------- launch ----------------
extern "C" void kernel_launch(void* const* d_in, const int* in_sizes, int n_in,
                              void* d_out, int out_size)
{
    const float* x     = (const float*)d_in[0];
    const int*   mask  = (const int*)d_in[1];
    const float* noise = (const float*)d_in[2];
    const float* Wr    = (const float*)d_in[3];
    const float* W1    = (const float*)d_in[4];
    const float* W2    = (const float*)d_in[5];
    float*       out   = (float*)d_out;

    const int  N = in_sizes[1];                      // 8192
    const int  D = in_sizes[0] / N;                  // 1024
    const int  E = in_sizes[2] / N;                  // 16
    const int  H = (int)((long)in_sizes[4] / ((long)E * D)); // 4096
    const int  cap = (int)((long)N * 5 / (4 * E));   // 640
    const long ytot = (long)N * D;

    cudaFuncSetAttribute(gemm_kernel<0>, cudaFuncAttributeMaxDynamicSharedMemorySize, GSMEM);
    cudaFuncSetAttribute(gemm_kernel<1>, cudaFuncAttributeMaxDynamicSharedMemorySize, GSMEM);
    cudaFuncSetAttribute(rank_kernel, cudaFuncAttributeMaxDynamicSharedMemorySize, 65536);

    init_kernel<<<(unsigned)((ytot / 4 + 255) / 256), 256>>>(out, ytot);
    router_kernel<<<N / 8, 256>>>(x, mask, noise, Wr, N, D);
    loss_reduce_kernel<<<1, 32>>>(out, N / 8, (long)out_size);
    scan_kernel<<<N / 256, 256>>>(mask, N);
    rank_kernel<<<E, 256, (size_t)N * 8>>>(cap);

    ushort_t *xhi, *xlo, *w1h, *w2h;
    cudaGetSymbolAddress((void**)&xhi, g_xhi);
    cudaGetSymbolAddress((void**)&xlo, g_xlo);
    cudaGetSymbolAddress((void**)&w1h, g_w1h);
    cudaGetSymbolAddress((void**)&w2h, g_w2h);

    pack_split_kernel<<<2048, 256>>>(x, xhi, xlo, (long)N * D / 4);
    pack_single_kernel<<<4096, 256>>>(W1, w1h, (long)E * D * H / 4);
    pack_single_kernel<<<4096, 256>>>(W2, w2h, (long)E * D * H / 4);

    gemm_kernel<0><<<E * (H / 128) * 5, 256, GSMEM>>>(x, out, cap);
    gemm_kernel<1><<<E * (D / 128) * 5, 256, GSMEM>>>(x, out, cap);
}

// round 10
// speedup vs baseline: 2.0687x; 1.3614x over previous
#include <cuda_runtime.h>
#include <cuda_fp16.h>
#include <cstdint>
#include <cstddef>

typedef unsigned short ushort_t;

#define NTOK 8192
#define EEXP 16
#define CAPS 640
#define RBLKS (NTOK/8)

// ---------------- static device scratch ----------------
__device__ ushort_t g_xh[(size_t)NTOK * 1024];
__device__ ushort_t g_w1h[(size_t)EEXP * 1024 * 4096];
__device__ ushort_t g_w2h[(size_t)EEXP * 4096 * 1024];
__device__ ushort_t g_hh[(size_t)EEXP * CAPS * 4096];
__device__ float g_gate[NTOK];
__device__ int   g_eid[NTOK];
__device__ int   g_cnt[EEXP];
__device__ int   g_lst_tok[EEXP * NTOK];
__device__ float g_lst_gate[EEXP * NTOK];
__device__ int   g_tok4slot[EEXP * CAPS];
__device__ float g_slotgate[EEXP * CAPS];
__device__ float g_pp[RBLKS * 16];
__device__ int   g_pf[RBLKS * 16];
__device__ float g_pz[RBLKS];
__device__ int   g_pn[RBLKS];

// ---------------- helpers ----------------
__device__ __forceinline__ uint32_t f2h(float f) {
    return (uint32_t)__half_as_ushort(__float2half_rn(f));
}
__device__ __forceinline__ uint32_t smem_u32(const void* p) {
    uint32_t a;
    asm("{ .reg .u64 t; cvta.to.shared.u64 t, %1; cvt.u32.u64 %0, t; }" : "=r"(a) : "l"(p));
    return a;
}
__device__ __forceinline__ void cpa16(uint32_t d, const void* s) {
    asm volatile("cp.async.cg.shared.global [%0], [%1], 16;" :: "r"(d), "l"(s));
}
__device__ __forceinline__ void cp_commit() { asm volatile("cp.async.commit_group;"); }
__device__ __forceinline__ void cp_wait0() { asm volatile("cp.async.wait_group 0;" ::: "memory"); }
__device__ __forceinline__ void cp_wait1() { asm volatile("cp.async.wait_group 1;" ::: "memory"); }
__device__ __forceinline__ void ldsm4(uint32_t* r, uint32_t a) {
    asm volatile("ldmatrix.sync.aligned.m8n8.x4.shared.b16 {%0,%1,%2,%3}, [%4];"
        : "=r"(r[0]), "=r"(r[1]), "=r"(r[2]), "=r"(r[3]) : "r"(a));
}
__device__ __forceinline__ void ldsm4t(uint32_t* r, uint32_t a) {
    asm volatile("ldmatrix.sync.aligned.m8n8.x4.trans.shared.b16 {%0,%1,%2,%3}, [%4];"
        : "=r"(r[0]), "=r"(r[1]), "=r"(r[2]), "=r"(r[3]) : "r"(a));
}
__device__ __forceinline__ void mmaf16(float* c, const uint32_t* a, uint32_t b0, uint32_t b1) {
    asm volatile("mma.sync.aligned.m16n8k16.row.col.f32.f16.f16.f32 "
        "{%0,%1,%2,%3}, {%4,%5,%6,%7}, {%8,%9}, {%0,%1,%2,%3};"
        : "+f"(c[0]), "+f"(c[1]), "+f"(c[2]), "+f"(c[3])
        : "r"(a[0]), "r"(a[1]), "r"(a[2]), "r"(a[3]), "r"(b0), "r"(b1));
}

// ---------------- init: zero y + expert counters ----------------
__global__ void init_kernel(float* __restrict__ out, long ytot) {
    if (blockIdx.x == 0 && threadIdx.x < EEXP) g_cnt[threadIdx.x] = 0;
    long i4 = (long)blockIdx.x * blockDim.x + threadIdx.x;
    long n4 = ytot >> 2;
    long stride = (long)gridDim.x * blockDim.x;
    float4 z = make_float4(0.f, 0.f, 0.f, 0.f);
    for (; i4 < n4; i4 += stride) reinterpret_cast<float4*>(out)[i4] = z;
}

// ---------------- fp16 pack ----------------
__global__ void pack_kernel(const float* __restrict__ in, ushort_t* __restrict__ h, long n4)
{
    long i = (long)blockIdx.x * blockDim.x + threadIdx.x;
    long stride = (long)gridDim.x * blockDim.x;
    for (; i < n4; i += stride) {
        float4 v = reinterpret_cast<const float4*>(in)[i];
        uint32_t hx = f2h(v.x), hy = f2h(v.y), hz = f2h(v.z), hw = f2h(v.w);
        reinterpret_cast<uint2*>(h)[i] = make_uint2(hx | (hy << 16), hz | (hw << 16));
    }
}

// ---------------- router ----------------
__global__ void __launch_bounds__(256) router_kernel(
    const float* __restrict__ x, const int* __restrict__ mask,
    const float* __restrict__ noise, const float* __restrict__ Wr, int N, int D)
{
    int warp = threadIdx.x >> 5, lane = threadIdx.x & 31;
    int t = blockIdx.x * 8 + warp;
    __shared__ float s_log[8][16];
    __shared__ float s_p[16]; __shared__ int s_f[16];
    __shared__ float s_z; __shared__ int s_n;
    if (threadIdx.x < 16) { s_p[threadIdx.x] = 0.f; s_f[threadIdx.x] = 0; }
    if (threadIdx.x == 0) { s_z = 0.f; s_n = 0; }
    __syncthreads();
    if (t < N) {
        float acc[16];
#pragma unroll
        for (int e = 0; e < 16; ++e) acc[e] = 0.f;
        const float* xr = x + (size_t)t * D;
        for (int d = lane; d < D; d += 32) {
            float xv = xr[d];
            const float* w = Wr + (size_t)d * 16;
#pragma unroll
            for (int e = 0; e < 16; ++e) acc[e] = fmaf(xv, w[e], acc[e]);
        }
#pragma unroll
        for (int e = 0; e < 16; ++e) {
            float v = acc[e];
#pragma unroll
            for (int o = 16; o; o >>= 1) v += __shfl_xor_sync(0xFFFFFFFFu, v, o);
            if (lane == 0) s_log[warp][e] = v;
        }
        __syncwarp();
        int e = lane & 15;
        float lc = s_log[warp][e];
        int mk = mask[t] ? 1 : 0;
        float nz = noise[(size_t)t * 16 + e];
        float mult = mk ? (1.0f + (nz * 2.0f - 1.0f) * 0.1f) : 1.0f;
        float ln = lc * mult;
        float mx = ln;
#pragma unroll
        for (int o = 8; o; o >>= 1) mx = fmaxf(mx, __shfl_xor_sync(0xFFFFFFFFu, mx, o, 16));
        unsigned bal = __ballot_sync(0xFFFFFFFFu, ln == mx);
        int eid = __ffs(bal) - 1;
        float se = expf(ln - mx);
#pragma unroll
        for (int o = 8; o; o >>= 1) se += __shfl_xor_sync(0xFFFFFFFFu, se, o, 16);
        float lse = mx + logf(se);
        float gate = expf(mx - lse);
        float mxc = lc;
#pragma unroll
        for (int o = 8; o; o >>= 1) mxc = fmaxf(mxc, __shfl_xor_sync(0xFFFFFFFFu, mxc, o, 16));
        unsigned balc = __ballot_sync(0xFFFFFFFFu, lc == mxc);
        int eidc = __ffs(balc) - 1;
        float sec = expf(lc - mxc);
#pragma unroll
        for (int o = 8; o; o >>= 1) sec += __shfl_xor_sync(0xFFFFFFFFu, sec, o, 16);
        float lsec = mxc + logf(sec);
        float pce = expf(lc - lsec);
        if (lane < 16 && mk) {
            atomicAdd(&s_p[e], pce);
            if (e == eidc) atomicAdd(&s_f[e], 1);
        }
        if (lane == 0) {
            g_gate[t] = gate; g_eid[t] = eid;
            if (mk) { atomicAdd(&s_z, lsec * lsec); atomicAdd(&s_n, 1); }
        }
    }
    __syncthreads();
    if (threadIdx.x < 16) {
        g_pp[blockIdx.x * 16 + threadIdx.x] = s_p[threadIdx.x];
        g_pf[blockIdx.x * 16 + threadIdx.x] = s_f[threadIdx.x];
    }
    if (threadIdx.x == 0) { g_pz[blockIdx.x] = s_z; g_pn[blockIdx.x] = s_n; }
}

__global__ void loss_reduce_kernel(float* __restrict__ out, int nb, long outsz) {
    __shared__ float sp[16], sf[16], szn[2];
    int tid = threadIdx.x;
    if (tid < 16) {
        float s = 0.f; int c = 0;
        for (int b = 0; b < nb; ++b) { s += g_pp[b * 16 + tid]; c += g_pf[b * 16 + tid]; }
        sp[tid] = s; sf[tid] = (float)c;
    }
    if (tid == 16) { float s = 0.f; for (int b = 0; b < nb; ++b) s += g_pz[b]; szn[0] = s; }
    if (tid == 17) { int c = 0; for (int b = 0; b < nb; ++b) c += g_pn[b]; szn[1] = (float)c; }
    __syncthreads();
    if (tid == 0) {
        float n = szn[1], lb = 0.f;
        for (int e = 0; e < 16; ++e) lb += (sp[e] / n) * (sf[e] / n);
        out[outsz - 2] = lb * 16.0f;
        out[outsz - 1] = szn[0] / n;
    }
}

// ---------------- dispatch: parallel scan + per-expert rank ----------------
__global__ void __launch_bounds__(256) scan_kernel(const int* __restrict__ mask, int N)
{
    int t = blockIdx.x * blockDim.x + threadIdx.x;
    if (t < N && mask[t]) {
        int e = g_eid[t];
        int i = atomicAdd(&g_cnt[e], 1);
        g_lst_tok[e * NTOK + i] = t;
        g_lst_gate[e * NTOK + i] = g_gate[t];
    }
}

__global__ void __launch_bounds__(256) rank_kernel(int cap)
{
    extern __shared__ char dsm[];
    float* sg = (float*)dsm;
    int*   st = (int*)(dsm + (size_t)NTOK * 4);
    int e = blockIdx.x, tid = threadIdx.x;
    for (int i = tid; i < cap; i += 256) {
        g_tok4slot[e * cap + i] = -1;
        g_slotgate[e * cap + i] = 0.f;
    }
    int cnt = g_cnt[e];
    for (int i = tid; i < cnt; i += 256) {
        st[i] = g_lst_tok[e * NTOK + i];
        sg[i] = g_lst_gate[e * NTOK + i];
    }
    __syncthreads();
    for (int i = tid; i < cnt; i += 256) {
        int ti = st[i]; float gi = sg[i];
        int r = 0;
        for (int j = 0; j < cnt; ++j) {
            float gj = sg[j]; int tj = st[j];
            r += (gj > gi) || (gj == gi && tj < ti);
        }
        if (r < cap) {
            g_tok4slot[e * cap + r] = ti;
            g_slotgate[e * cap + r] = gi;
        }
    }
}

// ---------------- fp16 single-pass tensor-core GEMM ----------------
// CTA tile 128m x 128n, BK=32, 8 warps (4m x 2n), warp tile 32x64.
// 2-stage cp.async pipeline (round-5 proven structure).
// MODE 0: h = relu(gather(x) @ W1[e]); MODE 1: y = (h @ W2[e]) * gate
#define STG 18432
#define ABUF(s) ((s) * STG)
#define BBUF(s) ((s) * STG + 10240)
#define GSMEM (2 * STG)

template<int MODE>
__global__ void __launch_bounds__(256, 2) gemm_kernel(
    const float* __restrict__ xunused, float* __restrict__ y, int cap)
{
    const int K   = (MODE == 0) ? 1024 : 4096;
    const int NT  = (MODE == 0) ? 32 : 8;
    const int Nn  = (MODE == 0) ? 4096 : 1024;
    const int NCH = K / 32;

    int b = blockIdx.x;
    const int m  = b % 5; b /= 5;
    const int n  = b % NT;
    const int e  = b / NT;
    const int m0 = m * 128, n0 = n * 128;

    extern __shared__ char smem[];
    const uint32_t sb = smem_u32(smem);
    __shared__ int s_arow[128];

    const int tid = threadIdx.x, wid = tid >> 5, lane = tid & 31;
    const int wm = wid & 3, wn = wid >> 2;

    if (tid < 128) {
        if (MODE == 0) {
            int tok = g_tok4slot[e * cap + m0 + tid];
            s_arow[tid] = (tok >= 0) ? tok : 0;
        } else {
            s_arow[tid] = e * CAPS + m0 + tid;
        }
    }
    __syncthreads();

    const ushort_t* AH = (MODE == 0) ? g_xh : g_hh;
    const ushort_t* BH = ((MODE == 0) ? g_w1h : g_w2h) + (size_t)e * K * Nn;

    // per-thread fixed load coordinates
    const int ar0 = tid >> 2, ac0 = tid & 3;
    const int ar1 = (tid + 256) >> 2;
    const int bk0 = tid >> 4, bc0 = tid & 15;
    const int bk1 = (tid + 256) >> 4, bc1 = tid & 15;
    const ushort_t* aH0 = AH + (size_t)s_arow[ar0] * K + ac0 * 8;
    const ushort_t* aH1 = AH + (size_t)s_arow[ar1] * K + ac0 * 8;
    const ushort_t* bH0 = BH + (size_t)bk0 * Nn + n0 + bc0 * 8;
    const ushort_t* bH1 = BH + (size_t)bk1 * Nn + n0 + bc1 * 8;
    const uint32_t aoff0 = ar0 * 80 + ac0 * 16, aoff1 = ar1 * 80 + ac0 * 16;
    const uint32_t boff0 = bk0 * 256 + ((bc0 ^ (bk0 & 7)) << 4);
    const uint32_t boff1 = bk1 * 256 + ((bc1 ^ (bk1 & 7)) << 4);

    float acc[2][8][4];
#pragma unroll
    for (int i = 0; i < 2; ++i)
#pragma unroll
        for (int j = 0; j < 8; ++j)
#pragma unroll
            for (int q = 0; q < 4; ++q) acc[i][j][q] = 0.f;

    auto issue = [&](int kt, int buf) {
        const long ka = (long)kt * 32;
        cpa16(sb + ABUF(buf) + aoff0, aH0 + ka);
        cpa16(sb + ABUF(buf) + aoff1, aH1 + ka);
        const long kb = (long)kt * 32 * Nn;
        cpa16(sb + BBUF(buf) + boff0, bH0 + kb);
        cpa16(sb + BBUF(buf) + boff1, bH1 + kb);
        cp_commit();
    };

    issue(0, 0);

    const uint32_t a_row = (lane & 15), a_kq = (lane >> 4);
    const uint32_t b_kr = (lane & 7) + (lane >> 4) * 8;
    const uint32_t b_nc = wn * 8 + ((lane >> 3) & 1);

    for (int kt = 0; kt < NCH; ++kt) {
        const int buf = kt & 1;
        if (kt + 1 < NCH) { issue(kt + 1, buf ^ 1); cp_wait1(); }
        else cp_wait0();
        __syncthreads();

        const uint32_t aB = sb + ABUF(buf);
        const uint32_t bB = sb + BBUF(buf);

#pragma unroll
        for (int ks = 0; ks < 2; ++ks) {
            uint32_t fA[2][4];
#pragma unroll
            for (int tm = 0; tm < 2; ++tm) {
                uint32_t ao = (wm * 32 + tm * 16 + a_row) * 80 + (ks * 16 + a_kq * 8) * 2;
                ldsm4(fA[tm], aB + ao);
            }
            const uint32_t kr = ks * 16 + b_kr;
            const uint32_t krl = kr & 7;
#pragma unroll
            for (int nb = 0; nb < 4; ++nb) {
                uint32_t nc = b_nc + nb * 2;
                uint32_t bo = kr * 256 + ((nc ^ krl) << 4);
                uint32_t fB[4];
                ldsm4t(fB, bB + bo);
#pragma unroll
                for (int tm = 0; tm < 2; ++tm) {
                    mmaf16(acc[tm][nb * 2 + 0], fA[tm], fB[0], fB[2]);
                    mmaf16(acc[tm][nb * 2 + 1], fA[tm], fB[1], fB[3]);
                }
            }
        }
        __syncthreads();
    }

    // ---- epilogue ----
    const int gid = lane >> 2, tig = lane & 3;
#pragma unroll
    for (int tm = 0; tm < 2; ++tm) {
        const int r0 = m0 + wm * 32 + tm * 16 + gid;
#pragma unroll
        for (int j = 0; j < 8; ++j) {
            const int col = n0 + wn * 64 + j * 8 + tig * 2;
            if (MODE == 0) {
#pragma unroll
                for (int hh = 0; hh < 2; ++hh) {
                    int row = r0 + hh * 8;
                    float v0 = fmaxf(acc[tm][j][hh * 2 + 0], 0.f);
                    float v1 = fmaxf(acc[tm][j][hh * 2 + 1], 0.f);
                    uint32_t h0 = f2h(v0), h1 = f2h(v1);
                    size_t idx = (size_t)(e * CAPS + row) * 4096 + col;
                    *(uint32_t*)(g_hh + idx) = h0 | (h1 << 16);
                }
            } else {
#pragma unroll
                for (int hh = 0; hh < 2; ++hh) {
                    int row = r0 + hh * 8;
                    int slot = e * cap + row;
                    int tok = g_tok4slot[slot];
                    if (tok >= 0) {
                        float g = g_slotgate[slot];
                        float2 v;
                        v.x = acc[tm][j][hh * 2 + 0] * g;
                        v.y = acc[tm][j][hh * 2 + 1] * g;
                        *(float2*)(y + (size_t)tok * 1024 + col) = v;
                    }
                }
            }
        }
    }
}

// ---------------- launch ----------------
extern "C" void kernel_launch(void* const* d_in, const int* in_sizes, int n_in,
                              void* d_out, int out_size)
{
    const float* x     = (const float*)d_in[0];
    const int*   mask  = (const int*)d_in[1];
    const float* noise = (const float*)d_in[2];
    const float* Wr    = (const float*)d_in[3];
    const float* W1    = (const float*)d_in[4];
    const float* W2    = (const float*)d_in[5];
    float*       out   = (float*)d_out;

    const int  N = in_sizes[1];                      // 8192
    const int  D = in_sizes[0] / N;                  // 1024
    const int  E = in_sizes[2] / N;                  // 16
    const int  H = (int)((long)in_sizes[4] / ((long)E * D)); // 4096
    const int  cap = (int)((long)N * 5 / (4 * E));   // 640
    const long ytot = (long)N * D;

    cudaFuncSetAttribute(gemm_kernel<0>, cudaFuncAttributeMaxDynamicSharedMemorySize, GSMEM);
    cudaFuncSetAttribute(gemm_kernel<1>, cudaFuncAttributeMaxDynamicSharedMemorySize, GSMEM);
    cudaFuncSetAttribute(rank_kernel, cudaFuncAttributeMaxDynamicSharedMemorySize, 65536);

    init_kernel<<<(unsigned)((ytot / 4 + 255) / 256), 256>>>(out, ytot);
    router_kernel<<<N / 8, 256>>>(x, mask, noise, Wr, N, D);
    loss_reduce_kernel<<<1, 32>>>(out, N / 8, (long)out_size);
    scan_kernel<<<N / 256, 256>>>(mask, N);
    rank_kernel<<<E, 256, (size_t)N * 8>>>(cap);

    ushort_t *xh, *w1h, *w2h;
    cudaGetSymbolAddress((void**)&xh, g_xh);
    cudaGetSymbolAddress((void**)&w1h, g_w1h);
    cudaGetSymbolAddress((void**)&w2h, g_w2h);

    pack_kernel<<<2048, 256>>>(x, xh, (long)N * D / 4);
    pack_kernel<<<4096, 256>>>(W1, w1h, (long)E * D * H / 4);
    pack_kernel<<<4096, 256>>>(W2, w2h, (long)E * D * H / 4);

    gemm_kernel<0><<<E * (H / 128) * 5, 256, GSMEM>>>(x, out, cap);
    gemm_kernel<1><<<E * (D / 128) * 5, 256, GSMEM>>>(x, out, cap);
}

// round 11
// speedup vs baseline: 2.3152x; 1.1191x over previous
#include <cuda_runtime.h>
#include <cuda_fp16.h>
#include <cstdint>
#include <cstddef>

typedef unsigned short ushort_t;

#define NTOK 8192
#define EEXP 16
#define CAPS 640
#define RBLKS (NTOK/8)

// ---------------- static device scratch ----------------
__device__ ushort_t g_xh[(size_t)NTOK * 1024];
__device__ ushort_t g_w1h[(size_t)EEXP * 1024 * 4096];
__device__ ushort_t g_w2h[(size_t)EEXP * 4096 * 1024];
__device__ ushort_t g_hh[(size_t)EEXP * CAPS * 4096];
__device__ float g_gate[NTOK];
__device__ int   g_eid[NTOK];
__device__ int   g_cnt[EEXP];
__device__ int   g_lst_tok[EEXP * NTOK];
__device__ float g_lst_gate[EEXP * NTOK];
__device__ int   g_tok4slot[EEXP * CAPS];
__device__ float g_slotgate[EEXP * CAPS];
__device__ float g_pp[RBLKS * 16];
__device__ int   g_pf[RBLKS * 16];
__device__ float g_pz[RBLKS];
__device__ int   g_pn[RBLKS];

// ---------------- helpers ----------------
__device__ __forceinline__ uint32_t f2h(float f) {
    return (uint32_t)__half_as_ushort(__float2half_rn(f));
}
__device__ __forceinline__ uint32_t smem_u32(const void* p) {
    uint32_t a;
    asm("{ .reg .u64 t; cvta.to.shared.u64 t, %1; cvt.u32.u64 %0, t; }" : "=r"(a) : "l"(p));
    return a;
}
__device__ __forceinline__ void cpa16(uint32_t d, const void* s) {
    asm volatile("cp.async.cg.shared.global [%0], [%1], 16;" :: "r"(d), "l"(s));
}
__device__ __forceinline__ void cp_commit() { asm volatile("cp.async.commit_group;"); }
__device__ __forceinline__ void cp_wait0() { asm volatile("cp.async.wait_group 0;" ::: "memory"); }
__device__ __forceinline__ void cp_wait1() { asm volatile("cp.async.wait_group 1;" ::: "memory"); }
__device__ __forceinline__ void ldsm4(uint32_t* r, uint32_t a) {
    asm volatile("ldmatrix.sync.aligned.m8n8.x4.shared.b16 {%0,%1,%2,%3}, [%4];"
        : "=r"(r[0]), "=r"(r[1]), "=r"(r[2]), "=r"(r[3]) : "r"(a));
}
__device__ __forceinline__ void ldsm4t(uint32_t* r, uint32_t a) {
    asm volatile("ldmatrix.sync.aligned.m8n8.x4.trans.shared.b16 {%0,%1,%2,%3}, [%4];"
        : "=r"(r[0]), "=r"(r[1]), "=r"(r[2]), "=r"(r[3]) : "r"(a));
}
__device__ __forceinline__ void mmaf16(float* c, const uint32_t* a, uint32_t b0, uint32_t b1) {
    asm volatile("mma.sync.aligned.m16n8k16.row.col.f32.f16.f16.f32 "
        "{%0,%1,%2,%3}, {%4,%5,%6,%7}, {%8,%9}, {%0,%1,%2,%3};"
        : "+f"(c[0]), "+f"(c[1]), "+f"(c[2]), "+f"(c[3])
        : "r"(a[0]), "r"(a[1]), "r"(a[2]), "r"(a[3]), "r"(b0), "r"(b1));
}

// ---------------- init: zero y + expert counters ----------------
__global__ void init_kernel(float* __restrict__ out, long ytot) {
    if (blockIdx.x == 0 && threadIdx.x < EEXP) g_cnt[threadIdx.x] = 0;
    long i4 = (long)blockIdx.x * blockDim.x + threadIdx.x;
    long n4 = ytot >> 2;
    long stride = (long)gridDim.x * blockDim.x;
    float4 z = make_float4(0.f, 0.f, 0.f, 0.f);
    for (; i4 < n4; i4 += stride) reinterpret_cast<float4*>(out)[i4] = z;
}

// ---------------- fp16 pack ----------------
__global__ void pack_kernel(const float* __restrict__ in, ushort_t* __restrict__ h, long n4)
{
    long i = (long)blockIdx.x * blockDim.x + threadIdx.x;
    long stride = (long)gridDim.x * blockDim.x;
    for (; i < n4; i += stride) {
        float4 v = reinterpret_cast<const float4*>(in)[i];
        uint32_t hx = f2h(v.x), hy = f2h(v.y), hz = f2h(v.z), hw = f2h(v.w);
        reinterpret_cast<uint2*>(h)[i] = make_uint2(hx | (hy << 16), hz | (hw << 16));
    }
}

// ---------------- router ----------------
__global__ void __launch_bounds__(256) router_kernel(
    const float* __restrict__ x, const int* __restrict__ mask,
    const float* __restrict__ noise, const float* __restrict__ Wr, int N, int D)
{
    int warp = threadIdx.x >> 5, lane = threadIdx.x & 31;
    int t = blockIdx.x * 8 + warp;
    __shared__ float s_log[8][16];
    __shared__ float s_p[16]; __shared__ int s_f[16];
    __shared__ float s_z; __shared__ int s_n;
    if (threadIdx.x < 16) { s_p[threadIdx.x] = 0.f; s_f[threadIdx.x] = 0; }
    if (threadIdx.x == 0) { s_z = 0.f; s_n = 0; }
    __syncthreads();
    if (t < N) {
        float acc[16];
#pragma unroll
        for (int e = 0; e < 16; ++e) acc[e] = 0.f;
        const float* xr = x + (size_t)t * D;
        for (int d = lane; d < D; d += 32) {
            float xv = xr[d];
            const float* w = Wr + (size_t)d * 16;
#pragma unroll
            for (int e = 0; e < 16; ++e) acc[e] = fmaf(xv, w[e], acc[e]);
        }
#pragma unroll
        for (int e = 0; e < 16; ++e) {
            float v = acc[e];
#pragma unroll
            for (int o = 16; o; o >>= 1) v += __shfl_xor_sync(0xFFFFFFFFu, v, o);
            if (lane == 0) s_log[warp][e] = v;
        }
        __syncwarp();
        int e = lane & 15;
        float lc = s_log[warp][e];
        int mk = mask[t] ? 1 : 0;
        float nz = noise[(size_t)t * 16 + e];
        float mult = mk ? (1.0f + (nz * 2.0f - 1.0f) * 0.1f) : 1.0f;
        float ln = lc * mult;
        float mx = ln;
#pragma unroll
        for (int o = 8; o; o >>= 1) mx = fmaxf(mx, __shfl_xor_sync(0xFFFFFFFFu, mx, o, 16));
        unsigned bal = __ballot_sync(0xFFFFFFFFu, ln == mx);
        int eid = __ffs(bal) - 1;
        float se = expf(ln - mx);
#pragma unroll
        for (int o = 8; o; o >>= 1) se += __shfl_xor_sync(0xFFFFFFFFu, se, o, 16);
        float lse = mx + logf(se);
        float gate = expf(mx - lse);
        float mxc = lc;
#pragma unroll
        for (int o = 8; o; o >>= 1) mxc = fmaxf(mxc, __shfl_xor_sync(0xFFFFFFFFu, mxc, o, 16));
        unsigned balc = __ballot_sync(0xFFFFFFFFu, lc == mxc);
        int eidc = __ffs(balc) - 1;
        float sec = expf(lc - mxc);
#pragma unroll
        for (int o = 8; o; o >>= 1) sec += __shfl_xor_sync(0xFFFFFFFFu, sec, o, 16);
        float lsec = mxc + logf(sec);
        float pce = expf(lc - lsec);
        if (lane < 16 && mk) {
            atomicAdd(&s_p[e], pce);
            if (e == eidc) atomicAdd(&s_f[e], 1);
        }
        if (lane == 0) {
            g_gate[t] = gate; g_eid[t] = eid;
            if (mk) { atomicAdd(&s_z, lsec * lsec); atomicAdd(&s_n, 1); }
        }
    }
    __syncthreads();
    if (threadIdx.x < 16) {
        g_pp[blockIdx.x * 16 + threadIdx.x] = s_p[threadIdx.x];
        g_pf[blockIdx.x * 16 + threadIdx.x] = s_f[threadIdx.x];
    }
    if (threadIdx.x == 0) { g_pz[blockIdx.x] = s_z; g_pn[blockIdx.x] = s_n; }
}

__global__ void loss_reduce_kernel(float* __restrict__ out, int nb, long outsz) {
    __shared__ float sp[16], sf[16], szn[2];
    int tid = threadIdx.x;
    if (tid < 16) {
        float s = 0.f; int c = 0;
        for (int b = 0; b < nb; ++b) { s += g_pp[b * 16 + tid]; c += g_pf[b * 16 + tid]; }
        sp[tid] = s; sf[tid] = (float)c;
    }
    if (tid == 16) { float s = 0.f; for (int b = 0; b < nb; ++b) s += g_pz[b]; szn[0] = s; }
    if (tid == 17) { int c = 0; for (int b = 0; b < nb; ++b) c += g_pn[b]; szn[1] = (float)c; }
    __syncthreads();
    if (tid == 0) {
        float n = szn[1], lb = 0.f;
        for (int e = 0; e < 16; ++e) lb += (sp[e] / n) * (sf[e] / n);
        out[outsz - 2] = lb * 16.0f;
        out[outsz - 1] = szn[0] / n;
    }
}

// ---------------- dispatch: parallel scan + per-expert rank ----------------
__global__ void __launch_bounds__(256) scan_kernel(const int* __restrict__ mask, int N)
{
    int t = blockIdx.x * blockDim.x + threadIdx.x;
    if (t < N && mask[t]) {
        int e = g_eid[t];
        int i = atomicAdd(&g_cnt[e], 1);
        g_lst_tok[e * NTOK + i] = t;
        g_lst_gate[e * NTOK + i] = g_gate[t];
    }
}

__global__ void __launch_bounds__(256) rank_kernel(int cap)
{
    extern __shared__ char dsm[];
    float* sg = (float*)dsm;
    int*   st = (int*)(dsm + (size_t)NTOK * 4);
    int e = blockIdx.x, tid = threadIdx.x;
    for (int i = tid; i < cap; i += 256) {
        g_tok4slot[e * cap + i] = -1;
        g_slotgate[e * cap + i] = 0.f;
    }
    int cnt = g_cnt[e];
    for (int i = tid; i < cnt; i += 256) {
        st[i] = g_lst_tok[e * NTOK + i];
        sg[i] = g_lst_gate[e * NTOK + i];
    }
    __syncthreads();
    for (int i = tid; i < cnt; i += 256) {
        int ti = st[i]; float gi = sg[i];
        int r = 0;
        for (int j = 0; j < cnt; ++j) {
            float gj = sg[j]; int tj = st[j];
            r += (gj > gi) || (gj == gi && tj < ti);
        }
        if (r < cap) {
            g_tok4slot[e * cap + r] = ti;
            g_slotgate[e * cap + r] = gi;
        }
    }
}

// ---------------- fp16 single-pass tensor-core GEMM, BK=64 ----------------
// CTA tile 128m x 128n, BK=64, 8 warps (4m x 2n), warp tile 32x64.
// 2-stage cp.async pipeline; half the barriers of BK=32.
// A smem: 128 rows x 144B pitch (64 fp16 + 16B pad). B: 64 rows x 256B swizzled.
// MODE 0: h = relu(gather(x) @ W1[e]); MODE 1: y = (h @ W2[e]) * gate
#define APITCH 144
#define STG (128 * APITCH + 64 * 256)   // 18432 + 16384 = 34816
#define ABUF(s) ((s) * STG)
#define BBUF(s) ((s) * STG + 128 * APITCH)
#define GSMEM (2 * STG)

template<int MODE>
__global__ void __launch_bounds__(256, 2) gemm_kernel(
    const float* __restrict__ xunused, float* __restrict__ y, int cap)
{
    const int K   = (MODE == 0) ? 1024 : 4096;
    const int NT  = (MODE == 0) ? 32 : 8;
    const int Nn  = (MODE == 0) ? 4096 : 1024;
    const int NCH = K / 64;

    int b = blockIdx.x;
    const int m  = b % 5; b /= 5;
    const int n  = b % NT;
    const int e  = b / NT;
    const int m0 = m * 128, n0 = n * 128;

    extern __shared__ char smem[];
    const uint32_t sb = smem_u32(smem);
    __shared__ int s_arow[128];

    const int tid = threadIdx.x, wid = tid >> 5, lane = tid & 31;
    const int wm = wid & 3, wn = wid >> 2;

    if (tid < 128) {
        if (MODE == 0) {
            int tok = g_tok4slot[e * cap + m0 + tid];
            s_arow[tid] = (tok >= 0) ? tok : 0;
        } else {
            s_arow[tid] = e * CAPS + m0 + tid;
        }
    }
    __syncthreads();

    const ushort_t* AH = (MODE == 0) ? g_xh : g_hh;
    const ushort_t* BH = ((MODE == 0) ? g_w1h : g_w2h) + (size_t)e * K * Nn;

    // per-thread cp.async coordinates: 4 slots each for A and B
    // A: 128 rows x 8 chunks of 16B (= 64 fp16); slot = row*8 + cc
    // B: 64 rows x 16 chunks of 16B (= 128 fp16); slot = row*16 + cc
    const ushort_t* aP[4];
    const ushort_t* bP[4];
    uint32_t aOff[4], bOff[4];
#pragma unroll
    for (int i = 0; i < 4; ++i) {
        int ia = tid + i * 256;
        int ar = ia >> 3, ac = ia & 7;
        aP[i] = AH + (size_t)s_arow[ar] * K + ac * 8;
        aOff[i] = ar * APITCH + ac * 16;
        int br = ia >> 4, bc = ia & 15;
        bP[i] = BH + (size_t)br * Nn + n0 + bc * 8;
        bOff[i] = br * 256 + ((bc ^ (br & 7)) << 4);
    }

    float acc[2][8][4];
#pragma unroll
    for (int i = 0; i < 2; ++i)
#pragma unroll
        for (int j = 0; j < 8; ++j)
#pragma unroll
            for (int q = 0; q < 4; ++q) acc[i][j][q] = 0.f;

    auto issue = [&](int kt, int buf) {
        const long ka = (long)kt * 64;
        const long kb = (long)kt * 64 * Nn;
#pragma unroll
        for (int i = 0; i < 4; ++i) cpa16(sb + ABUF(buf) + aOff[i], aP[i] + ka);
#pragma unroll
        for (int i = 0; i < 4; ++i) cpa16(sb + BBUF(buf) + bOff[i], bP[i] + kb);
        cp_commit();
    };

    issue(0, 0);

    const uint32_t a_row = (lane & 15), a_kq = (lane >> 4);
    const uint32_t b_kr = (lane & 7) + (lane >> 4) * 8;
    const uint32_t b_nc = wn * 8 + ((lane >> 3) & 1);

    for (int kt = 0; kt < NCH; ++kt) {
        const int buf = kt & 1;
        if (kt + 1 < NCH) { issue(kt + 1, buf ^ 1); cp_wait1(); }
        else cp_wait0();
        __syncthreads();

        const uint32_t aB = sb + ABUF(buf);
        const uint32_t bB = sb + BBUF(buf);

#pragma unroll
        for (int ks = 0; ks < 4; ++ks) {
            uint32_t fA[2][4];
#pragma unroll
            for (int tm = 0; tm < 2; ++tm) {
                uint32_t ao = (wm * 32 + tm * 16 + a_row) * APITCH + (ks * 16 + a_kq * 8) * 2;
                ldsm4(fA[tm], aB + ao);
            }
            const uint32_t kr = ks * 16 + b_kr;
            const uint32_t krl = kr & 7;
#pragma unroll
            for (int nb = 0; nb < 4; ++nb) {
                uint32_t nc = b_nc + nb * 2;
                uint32_t bo = kr * 256 + ((nc ^ krl) << 4);
                uint32_t fB[4];
                ldsm4t(fB, bB + bo);
#pragma unroll
                for (int tm = 0; tm < 2; ++tm) {
                    mmaf16(acc[tm][nb * 2 + 0], fA[tm], fB[0], fB[2]);
                    mmaf16(acc[tm][nb * 2 + 1], fA[tm], fB[1], fB[3]);
                }
            }
        }
        __syncthreads();
    }

    // ---- epilogue ----
    const int gid = lane >> 2, tig = lane & 3;
#pragma unroll
    for (int tm = 0; tm < 2; ++tm) {
        const int r0 = m0 + wm * 32 + tm * 16 + gid;
#pragma unroll
        for (int j = 0; j < 8; ++j) {
            const int col = n0 + wn * 64 + j * 8 + tig * 2;
            if (MODE == 0) {
#pragma unroll
                for (int hh = 0; hh < 2; ++hh) {
                    int row = r0 + hh * 8;
                    float v0 = fmaxf(acc[tm][j][hh * 2 + 0], 0.f);
                    float v1 = fmaxf(acc[tm][j][hh * 2 + 1], 0.f);
                    uint32_t h0 = f2h(v0), h1 = f2h(v1);
                    size_t idx = (size_t)(e * CAPS + row) * 4096 + col;
                    *(uint32_t*)(g_hh + idx) = h0 | (h1 << 16);
                }
            } else {
#pragma unroll
                for (int hh = 0; hh < 2; ++hh) {
                    int row = r0 + hh * 8;
                    int slot = e * cap + row;
                    int tok = g_tok4slot[slot];
                    if (tok >= 0) {
                        float g = g_slotgate[slot];
                        float2 v;
                        v.x = acc[tm][j][hh * 2 + 0] * g;
                        v.y = acc[tm][j][hh * 2 + 1] * g;
                        *(float2*)(y + (size_t)tok * 1024 + col) = v;
                    }
                }
            }
        }
    }
}

// ---------------- launch ----------------
extern "C" void kernel_launch(void* const* d_in, const int* in_sizes, int n_in,
                              void* d_out, int out_size)
{
    const float* x     = (const float*)d_in[0];
    const int*   mask  = (const int*)d_in[1];
    const float* noise = (const float*)d_in[2];
    const float* Wr    = (const float*)d_in[3];
    const float* W1    = (const float*)d_in[4];
    const float* W2    = (const float*)d_in[5];
    float*       out   = (float*)d_out;

    const int  N = in_sizes[1];                      // 8192
    const int  D = in_sizes[0] / N;                  // 1024
    const int  E = in_sizes[2] / N;                  // 16
    const int  H = (int)((long)in_sizes[4] / ((long)E * D)); // 4096
    const int  cap = (int)((long)N * 5 / (4 * E));   // 640
    const long ytot = (long)N * D;

    cudaFuncSetAttribute(gemm_kernel<0>, cudaFuncAttributeMaxDynamicSharedMemorySize, GSMEM);
    cudaFuncSetAttribute(gemm_kernel<1>, cudaFuncAttributeMaxDynamicSharedMemorySize, GSMEM);
    cudaFuncSetAttribute(rank_kernel, cudaFuncAttributeMaxDynamicSharedMemorySize, 65536);

    init_kernel<<<(unsigned)((ytot / 4 + 255) / 256), 256>>>(out, ytot);
    router_kernel<<<N / 8, 256>>>(x, mask, noise, Wr, N, D);
    loss_reduce_kernel<<<1, 32>>>(out, N / 8, (long)out_size);
    scan_kernel<<<N / 256, 256>>>(mask, N);
    rank_kernel<<<E, 256, (size_t)N * 8>>>(cap);

    ushort_t *xh, *w1h, *w2h;
    cudaGetSymbolAddress((void**)&xh, g_xh);
    cudaGetSymbolAddress((void**)&w1h, g_w1h);
    cudaGetSymbolAddress((void**)&w2h, g_w2h);

    pack_kernel<<<2048, 256>>>(x, xh, (long)N * D / 4);
    pack_kernel<<<4096, 256>>>(W1, w1h, (long)E * D * H / 4);
    pack_kernel<<<4096, 256>>>(W2, w2h, (long)E * D * H / 4);

    gemm_kernel<0><<<E * (H / 128) * 5, 256, GSMEM>>>(x, out, cap);
    gemm_kernel<1><<<E * (D / 128) * 5, 256, GSMEM>>>(x, out, cap);
}

// round 12
// speedup vs baseline: 2.3523x; 1.0160x over previous
#include <cuda_runtime.h>
#include <cuda_fp16.h>
#include <cstdint>
#include <cstddef>

typedef unsigned short ushort_t;

#define NTOK 8192
#define EEXP 16
#define CAPS 640
#define RBLKS (NTOK/8)

// ---------------- static device scratch ----------------
__device__ ushort_t g_xh[(size_t)NTOK * 1024];
__device__ ushort_t g_w1h[(size_t)EEXP * 1024 * 4096];
__device__ ushort_t g_w2h[(size_t)EEXP * 4096 * 1024];
__device__ ushort_t g_hh[(size_t)EEXP * CAPS * 4096];
__device__ float g_gate[NTOK];
__device__ int   g_eid[NTOK];
__device__ int   g_cnt[EEXP];
__device__ int   g_lst_tok[EEXP * NTOK];
__device__ float g_lst_gate[EEXP * NTOK];
__device__ int   g_tok4slot[EEXP * CAPS];
__device__ float g_slotgate[EEXP * CAPS];
__device__ float g_pp[RBLKS * 16];
__device__ int   g_pf[RBLKS * 16];
__device__ float g_pz[RBLKS];
__device__ int   g_pn[RBLKS];

// ---------------- helpers ----------------
__device__ __forceinline__ uint32_t f2h(float f) {
    return (uint32_t)__half_as_ushort(__float2half_rn(f));
}
__device__ __forceinline__ uint32_t smem_u32(const void* p) {
    uint32_t a;
    asm("{ .reg .u64 t; cvta.to.shared.u64 t, %1; cvt.u32.u64 %0, t; }" : "=r"(a) : "l"(p));
    return a;
}
__device__ __forceinline__ void cpa16(uint32_t d, const void* s) {
    asm volatile("cp.async.cg.shared.global [%0], [%1], 16;" :: "r"(d), "l"(s));
}
__device__ __forceinline__ void cp_commit() { asm volatile("cp.async.commit_group;"); }
__device__ __forceinline__ void cp_wait0() { asm volatile("cp.async.wait_group 0;" ::: "memory"); }
__device__ __forceinline__ void cp_wait1() { asm volatile("cp.async.wait_group 1;" ::: "memory"); }
__device__ __forceinline__ void ldsm4(uint32_t* r, uint32_t a) {
    asm volatile("ldmatrix.sync.aligned.m8n8.x4.shared.b16 {%0,%1,%2,%3}, [%4];"
        : "=r"(r[0]), "=r"(r[1]), "=r"(r[2]), "=r"(r[3]) : "r"(a));
}
__device__ __forceinline__ void ldsm4t(uint32_t* r, uint32_t a) {
    asm volatile("ldmatrix.sync.aligned.m8n8.x4.trans.shared.b16 {%0,%1,%2,%3}, [%4];"
        : "=r"(r[0]), "=r"(r[1]), "=r"(r[2]), "=r"(r[3]) : "r"(a));
}
__device__ __forceinline__ void mmaf16(float* c, const uint32_t* a, uint32_t b0, uint32_t b1) {
    asm volatile("mma.sync.aligned.m16n8k16.row.col.f32.f16.f16.f32 "
        "{%0,%1,%2,%3}, {%4,%5,%6,%7}, {%8,%9}, {%0,%1,%2,%3};"
        : "+f"(c[0]), "+f"(c[1]), "+f"(c[2]), "+f"(c[3])
        : "r"(a[0]), "r"(a[1]), "r"(a[2]), "r"(a[3]), "r"(b0), "r"(b1));
}

// ---------------- init: zero y + expert counters ----------------
__global__ void init_kernel(float* __restrict__ out, long ytot) {
    if (blockIdx.x == 0 && threadIdx.x < EEXP) g_cnt[threadIdx.x] = 0;
    long i4 = (long)blockIdx.x * blockDim.x + threadIdx.x;
    long n4 = ytot >> 2;
    long stride = (long)gridDim.x * blockDim.x;
    float4 z = make_float4(0.f, 0.f, 0.f, 0.f);
    for (; i4 < n4; i4 += stride) reinterpret_cast<float4*>(out)[i4] = z;
}

// ---------------- fp16 pack ----------------
__global__ void pack_kernel(const float* __restrict__ in, ushort_t* __restrict__ h, long n4)
{
    long i = (long)blockIdx.x * blockDim.x + threadIdx.x;
    long stride = (long)gridDim.x * blockDim.x;
    for (; i < n4; i += stride) {
        float4 v = reinterpret_cast<const float4*>(in)[i];
        uint32_t hx = f2h(v.x), hy = f2h(v.y), hz = f2h(v.z), hw = f2h(v.w);
        reinterpret_cast<uint2*>(h)[i] = make_uint2(hx | (hy << 16), hz | (hw << 16));
    }
}

// ---------------- router ----------------
__global__ void __launch_bounds__(256) router_kernel(
    const float* __restrict__ x, const int* __restrict__ mask,
    const float* __restrict__ noise, const float* __restrict__ Wr, int N, int D)
{
    int warp = threadIdx.x >> 5, lane = threadIdx.x & 31;
    int t = blockIdx.x * 8 + warp;
    __shared__ float s_log[8][16];
    __shared__ float s_p[16]; __shared__ int s_f[16];
    __shared__ float s_z; __shared__ int s_n;
    if (threadIdx.x < 16) { s_p[threadIdx.x] = 0.f; s_f[threadIdx.x] = 0; }
    if (threadIdx.x == 0) { s_z = 0.f; s_n = 0; }
    __syncthreads();
    if (t < N) {
        float acc[16];
#pragma unroll
        for (int e = 0; e < 16; ++e) acc[e] = 0.f;
        const float* xr = x + (size_t)t * D;
        for (int d = lane; d < D; d += 32) {
            float xv = xr[d];
            const float* w = Wr + (size_t)d * 16;
#pragma unroll
            for (int e = 0; e < 16; ++e) acc[e] = fmaf(xv, w[e], acc[e]);
        }
#pragma unroll
        for (int e = 0; e < 16; ++e) {
            float v = acc[e];
#pragma unroll
            for (int o = 16; o; o >>= 1) v += __shfl_xor_sync(0xFFFFFFFFu, v, o);
            if (lane == 0) s_log[warp][e] = v;
        }
        __syncwarp();
        int e = lane & 15;
        float lc = s_log[warp][e];
        int mk = mask[t] ? 1 : 0;
        float nz = noise[(size_t)t * 16 + e];
        float mult = mk ? (1.0f + (nz * 2.0f - 1.0f) * 0.1f) : 1.0f;
        float ln = lc * mult;
        float mx = ln;
#pragma unroll
        for (int o = 8; o; o >>= 1) mx = fmaxf(mx, __shfl_xor_sync(0xFFFFFFFFu, mx, o, 16));
        unsigned bal = __ballot_sync(0xFFFFFFFFu, ln == mx);
        int eid = __ffs(bal) - 1;
        float se = expf(ln - mx);
#pragma unroll
        for (int o = 8; o; o >>= 1) se += __shfl_xor_sync(0xFFFFFFFFu, se, o, 16);
        float lse = mx + logf(se);
        float gate = expf(mx - lse);
        float mxc = lc;
#pragma unroll
        for (int o = 8; o; o >>= 1) mxc = fmaxf(mxc, __shfl_xor_sync(0xFFFFFFFFu, mxc, o, 16));
        unsigned balc = __ballot_sync(0xFFFFFFFFu, lc == mxc);
        int eidc = __ffs(balc) - 1;
        float sec = expf(lc - mxc);
#pragma unroll
        for (int o = 8; o; o >>= 1) sec += __shfl_xor_sync(0xFFFFFFFFu, sec, o, 16);
        float lsec = mxc + logf(sec);
        float pce = expf(lc - lsec);
        if (lane < 16 && mk) {
            atomicAdd(&s_p[e], pce);
            if (e == eidc) atomicAdd(&s_f[e], 1);
        }
        if (lane == 0) {
            g_gate[t] = gate; g_eid[t] = eid;
            if (mk) { atomicAdd(&s_z, lsec * lsec); atomicAdd(&s_n, 1); }
        }
    }
    __syncthreads();
    if (threadIdx.x < 16) {
        g_pp[blockIdx.x * 16 + threadIdx.x] = s_p[threadIdx.x];
        g_pf[blockIdx.x * 16 + threadIdx.x] = s_f[threadIdx.x];
    }
    if (threadIdx.x == 0) { g_pz[blockIdx.x] = s_z; g_pn[blockIdx.x] = s_n; }
}

__global__ void loss_reduce_kernel(float* __restrict__ out, int nb, long outsz) {
    __shared__ float sp[16], sf[16], szn[2];
    int tid = threadIdx.x;
    if (tid < 16) {
        float s = 0.f; int c = 0;
        for (int b = 0; b < nb; ++b) { s += g_pp[b * 16 + tid]; c += g_pf[b * 16 + tid]; }
        sp[tid] = s; sf[tid] = (float)c;
    }
    if (tid == 16) { float s = 0.f; for (int b = 0; b < nb; ++b) s += g_pz[b]; szn[0] = s; }
    if (tid == 17) { int c = 0; for (int b = 0; b < nb; ++b) c += g_pn[b]; szn[1] = (float)c; }
    __syncthreads();
    if (tid == 0) {
        float n = szn[1], lb = 0.f;
        for (int e = 0; e < 16; ++e) lb += (sp[e] / n) * (sf[e] / n);
        out[outsz - 2] = lb * 16.0f;
        out[outsz - 1] = szn[0] / n;
    }
}

// ---------------- dispatch: parallel scan + per-expert rank ----------------
__global__ void __launch_bounds__(256) scan_kernel(const int* __restrict__ mask, int N)
{
    int t = blockIdx.x * blockDim.x + threadIdx.x;
    if (t < N && mask[t]) {
        int e = g_eid[t];
        int i = atomicAdd(&g_cnt[e], 1);
        g_lst_tok[e * NTOK + i] = t;
        g_lst_gate[e * NTOK + i] = g_gate[t];
    }
}

__global__ void __launch_bounds__(256) rank_kernel(int cap)
{
    extern __shared__ char dsm[];
    float* sg = (float*)dsm;
    int*   st = (int*)(dsm + (size_t)NTOK * 4);
    int e = blockIdx.x, tid = threadIdx.x;
    for (int i = tid; i < cap; i += 256) {
        g_tok4slot[e * cap + i] = -1;
        g_slotgate[e * cap + i] = 0.f;
    }
    int cnt = g_cnt[e];
    for (int i = tid; i < cnt; i += 256) {
        st[i] = g_lst_tok[e * NTOK + i];
        sg[i] = g_lst_gate[e * NTOK + i];
    }
    __syncthreads();
    for (int i = tid; i < cnt; i += 256) {
        int ti = st[i]; float gi = sg[i];
        int r = 0;
        for (int j = 0; j < cnt; ++j) {
            float gj = sg[j]; int tj = st[j];
            r += (gj > gi) || (gj == gi && tj < ti);
        }
        if (r < cap) {
            g_tok4slot[e * cap + r] = ti;
            g_slotgate[e * cap + r] = gi;
        }
    }
}

// ---------------- fp16 single-pass tensor-core GEMM, BK=64 ----------------
// CTA tile 128m x 128n, BK=64, 8 warps (4m x 2n), warp tile 32x64.
// 2-stage cp.async pipeline.
// MODE 0: h = relu(gather(x) @ W1[e]), KSPLIT=1, store epilogue.
// MODE 1: y += (h @ W2[e]) * gate over KSPLIT=4 K-segments, atomicAdd epilogue.
#define APITCH 144
#define STG (128 * APITCH + 64 * 256)   // 34816
#define ABUF(s) ((s) * STG)
#define BBUF(s) ((s) * STG + 128 * APITCH)
#define GSMEM (2 * STG)

template<int MODE, int KSPLIT>
__global__ void __launch_bounds__(256, 2) gemm_kernel(
    const float* __restrict__ xunused, float* __restrict__ y, int cap)
{
    const int KTOT = (MODE == 0) ? 1024 : 4096;
    const int KSEG = KTOT / KSPLIT;
    const int NT   = (MODE == 0) ? 32 : 8;
    const int Nn   = (MODE == 0) ? 4096 : 1024;
    const int NCH  = KSEG / 64;

    int b = blockIdx.x;
    const int m  = b % 5; b /= 5;
    const int n  = b % NT; b /= NT;
    const int kq = b % KSPLIT;
    const int e  = b / KSPLIT;
    const int m0 = m * 128, n0 = n * 128;

    extern __shared__ char smem[];
    const uint32_t sb = smem_u32(smem);
    __shared__ int s_arow[128];

    const int tid = threadIdx.x, wid = tid >> 5, lane = tid & 31;
    const int wm = wid & 3, wn = wid >> 2;

    if (tid < 128) {
        if (MODE == 0) {
            int tok = g_tok4slot[e * cap + m0 + tid];
            s_arow[tid] = (tok >= 0) ? tok : 0;
        } else {
            s_arow[tid] = e * CAPS + m0 + tid;
        }
    }
    __syncthreads();

    const ushort_t* AH = ((MODE == 0) ? g_xh : g_hh) + (size_t)kq * KSEG;
    const ushort_t* BH = ((MODE == 0) ? g_w1h : g_w2h)
                         + (size_t)e * KTOT * Nn + (size_t)kq * KSEG * Nn;

    // per-thread cp.async coordinates: 4 slots each for A and B
    const ushort_t* aP[4];
    const ushort_t* bP[4];
    uint32_t aOff[4], bOff[4];
#pragma unroll
    for (int i = 0; i < 4; ++i) {
        int ia = tid + i * 256;
        int ar = ia >> 3, ac = ia & 7;
        aP[i] = AH + (size_t)s_arow[ar] * KTOT + ac * 8;
        aOff[i] = ar * APITCH + ac * 16;
        int br = ia >> 4, bc = ia & 15;
        bP[i] = BH + (size_t)br * Nn + n0 + bc * 8;
        bOff[i] = br * 256 + ((bc ^ (br & 7)) << 4);
    }

    float acc[2][8][4];
#pragma unroll
    for (int i = 0; i < 2; ++i)
#pragma unroll
        for (int j = 0; j < 8; ++j)
#pragma unroll
            for (int q = 0; q < 4; ++q) acc[i][j][q] = 0.f;

    auto issue = [&](int kt, int buf) {
        const long ka = (long)kt * 64;
        const long kb = (long)kt * 64 * Nn;
#pragma unroll
        for (int i = 0; i < 4; ++i) cpa16(sb + ABUF(buf) + aOff[i], aP[i] + ka);
#pragma unroll
        for (int i = 0; i < 4; ++i) cpa16(sb + BBUF(buf) + bOff[i], bP[i] + kb);
        cp_commit();
    };

    issue(0, 0);

    const uint32_t a_row = (lane & 15), a_kq = (lane >> 4);
    const uint32_t b_kr = (lane & 7) + (lane >> 4) * 8;
    const uint32_t b_nc = wn * 8 + ((lane >> 3) & 1);

    for (int kt = 0; kt < NCH; ++kt) {
        const int buf = kt & 1;
        if (kt + 1 < NCH) { issue(kt + 1, buf ^ 1); cp_wait1(); }
        else cp_wait0();
        __syncthreads();

        const uint32_t aB = sb + ABUF(buf);
        const uint32_t bB = sb + BBUF(buf);

#pragma unroll
        for (int ks = 0; ks < 4; ++ks) {
            uint32_t fA[2][4];
#pragma unroll
            for (int tm = 0; tm < 2; ++tm) {
                uint32_t ao = (wm * 32 + tm * 16 + a_row) * APITCH + (ks * 16 + a_kq * 8) * 2;
                ldsm4(fA[tm], aB + ao);
            }
            const uint32_t kr = ks * 16 + b_kr;
            const uint32_t krl = kr & 7;
#pragma unroll
            for (int nb = 0; nb < 4; ++nb) {
                uint32_t nc = b_nc + nb * 2;
                uint32_t bo = kr * 256 + ((nc ^ krl) << 4);
                uint32_t fB[4];
                ldsm4t(fB, bB + bo);
#pragma unroll
                for (int tm = 0; tm < 2; ++tm) {
                    mmaf16(acc[tm][nb * 2 + 0], fA[tm], fB[0], fB[2]);
                    mmaf16(acc[tm][nb * 2 + 1], fA[tm], fB[1], fB[3]);
                }
            }
        }
        __syncthreads();
    }

    // ---- epilogue ----
    const int gid = lane >> 2, tig = lane & 3;
#pragma unroll
    for (int tm = 0; tm < 2; ++tm) {
        const int r0 = m0 + wm * 32 + tm * 16 + gid;
#pragma unroll
        for (int j = 0; j < 8; ++j) {
            const int col = n0 + wn * 64 + j * 8 + tig * 2;
            if (MODE == 0) {
#pragma unroll
                for (int hh = 0; hh < 2; ++hh) {
                    int row = r0 + hh * 8;
                    float v0 = fmaxf(acc[tm][j][hh * 2 + 0], 0.f);
                    float v1 = fmaxf(acc[tm][j][hh * 2 + 1], 0.f);
                    uint32_t h0 = f2h(v0), h1 = f2h(v1);
                    size_t idx = (size_t)(e * CAPS + row) * 4096 + col;
                    *(uint32_t*)(g_hh + idx) = h0 | (h1 << 16);
                }
            } else {
#pragma unroll
                for (int hh = 0; hh < 2; ++hh) {
                    int row = r0 + hh * 8;
                    int slot = e * cap + row;
                    int tok = g_tok4slot[slot];
                    if (tok >= 0) {
                        float g = g_slotgate[slot];
                        float* dst = y + (size_t)tok * 1024 + col;
                        atomicAdd(dst + 0, acc[tm][j][hh * 2 + 0] * g);
                        atomicAdd(dst + 1, acc[tm][j][hh * 2 + 1] * g);
                    }
                }
            }
        }
    }
}

// ---------------- launch ----------------
extern "C" void kernel_launch(void* const* d_in, const int* in_sizes, int n_in,
                              void* d_out, int out_size)
{
    const float* x     = (const float*)d_in[0];
    const int*   mask  = (const int*)d_in[1];
    const float* noise = (const float*)d_in[2];
    const float* Wr    = (const float*)d_in[3];
    const float* W1    = (const float*)d_in[4];
    const float* W2    = (const float*)d_in[5];
    float*       out   = (float*)d_out;

    const int  N = in_sizes[1];                      // 8192
    const int  D = in_sizes[0] / N;                  // 1024
    const int  E = in_sizes[2] / N;                  // 16
    const int  H = (int)((long)in_sizes[4] / ((long)E * D)); // 4096
    const int  cap = (int)((long)N * 5 / (4 * E));   // 640
    const long ytot = (long)N * D;

    cudaFuncSetAttribute((const void*)gemm_kernel<0,1>, cudaFuncAttributeMaxDynamicSharedMemorySize, GSMEM);
    cudaFuncSetAttribute((const void*)gemm_kernel<1,4>, cudaFuncAttributeMaxDynamicSharedMemorySize, GSMEM);
    cudaFuncSetAttribute(rank_kernel, cudaFuncAttributeMaxDynamicSharedMemorySize, 65536);

    init_kernel<<<(unsigned)((ytot / 4 + 255) / 256), 256>>>(out, ytot);
    router_kernel<<<N / 8, 256>>>(x, mask, noise, Wr, N, D);
    loss_reduce_kernel<<<1, 32>>>(out, N / 8, (long)out_size);
    scan_kernel<<<N / 256, 256>>>(mask, N);
    rank_kernel<<<E, 256, (size_t)N * 8>>>(cap);

    ushort_t *xh, *w1h, *w2h;
    cudaGetSymbolAddress((void**)&xh, g_xh);
    cudaGetSymbolAddress((void**)&w1h, g_w1h);
    cudaGetSymbolAddress((void**)&w2h, g_w2h);

    pack_kernel<<<2048, 256>>>(x, xh, (long)N * D / 4);
    pack_kernel<<<4096, 256>>>(W1, w1h, (long)E * D * H / 4);
    pack_kernel<<<4096, 256>>>(W2, w2h, (long)E * D * H / 4);

    gemm_kernel<0,1><<<E * (H / 128) * 5, 256, GSMEM>>>(x, out, cap);
    gemm_kernel<1,4><<<E * (D / 128) * 5 * 4, 256, GSMEM>>>(x, out, cap);
}

// round 13
// speedup vs baseline: 2.6640x; 1.1325x over previous
#include <cuda_runtime.h>
#include <cuda_fp16.h>
#include <cstdint>
#include <cstddef>

typedef unsigned short ushort_t;

#define NTOK 8192
#define EEXP 16
#define CAPS 640
#define RBLKS (NTOK/8)

// ---------------- static device scratch ----------------
__device__ ushort_t g_xh[(size_t)NTOK * 1024];
__device__ ushort_t g_w1h[(size_t)EEXP * 1024 * 4096];
__device__ ushort_t g_w2h[(size_t)EEXP * 4096 * 1024];
__device__ ushort_t g_hh[(size_t)EEXP * CAPS * 4096];
__device__ float g_gate[NTOK];
__device__ int   g_cnt[EEXP];
__device__ int   g_lst_tok[EEXP * NTOK];
__device__ float g_lst_gate[EEXP * NTOK];
__device__ int   g_tok4slot[EEXP * CAPS];
__device__ float g_slotgate[EEXP * CAPS];
__device__ float g_pp[RBLKS * 16];
__device__ int   g_pf[RBLKS * 16];
__device__ float g_pz[RBLKS];
__device__ int   g_pn[RBLKS];

// ---------------- helpers ----------------
__device__ __forceinline__ uint32_t f2h(float f) {
    return (uint32_t)__half_as_ushort(__float2half_rn(f));
}
__device__ __forceinline__ uint32_t smem_u32(const void* p) {
    uint32_t a;
    asm("{ .reg .u64 t; cvta.to.shared.u64 t, %1; cvt.u32.u64 %0, t; }" : "=r"(a) : "l"(p));
    return a;
}
__device__ __forceinline__ void cpa16(uint32_t d, const void* s) {
    asm volatile("cp.async.cg.shared.global [%0], [%1], 16;" :: "r"(d), "l"(s));
}
__device__ __forceinline__ void cp_commit() { asm volatile("cp.async.commit_group;"); }
__device__ __forceinline__ void cp_wait0() { asm volatile("cp.async.wait_group 0;" ::: "memory"); }
__device__ __forceinline__ void cp_wait1() { asm volatile("cp.async.wait_group 1;" ::: "memory"); }
__device__ __forceinline__ void ldsm4(uint32_t* r, uint32_t a) {
    asm volatile("ldmatrix.sync.aligned.m8n8.x4.shared.b16 {%0,%1,%2,%3}, [%4];"
        : "=r"(r[0]), "=r"(r[1]), "=r"(r[2]), "=r"(r[3]) : "r"(a));
}
__device__ __forceinline__ void ldsm4t(uint32_t* r, uint32_t a) {
    asm volatile("ldmatrix.sync.aligned.m8n8.x4.trans.shared.b16 {%0,%1,%2,%3}, [%4];"
        : "=r"(r[0]), "=r"(r[1]), "=r"(r[2]), "=r"(r[3]) : "r"(a));
}
__device__ __forceinline__ void mmaf16(float* c, const uint32_t* a, uint32_t b0, uint32_t b1) {
    asm volatile("mma.sync.aligned.m16n8k16.row.col.f32.f16.f16.f32 "
        "{%0,%1,%2,%3}, {%4,%5,%6,%7}, {%8,%9}, {%0,%1,%2,%3};"
        : "+f"(c[0]), "+f"(c[1]), "+f"(c[2]), "+f"(c[3])
        : "r"(a[0]), "r"(a[1]), "r"(a[2]), "r"(a[3]), "r"(b0), "r"(b1));
}

// ---------------- init: zero y + expert counters ----------------
__global__ void init_kernel(float* __restrict__ out, long ytot) {
    if (blockIdx.x == 0 && threadIdx.x < EEXP) g_cnt[threadIdx.x] = 0;
    long i4 = (long)blockIdx.x * blockDim.x + threadIdx.x;
    long n4 = ytot >> 2;
    long stride = (long)gridDim.x * blockDim.x;
    float4 z = make_float4(0.f, 0.f, 0.f, 0.f);
    for (; i4 < n4; i4 += stride) reinterpret_cast<float4*>(out)[i4] = z;
}

// ---------------- fp16 pack ----------------
__global__ void pack_kernel(const float* __restrict__ in, ushort_t* __restrict__ h, long n4)
{
    long i = (long)blockIdx.x * blockDim.x + threadIdx.x;
    long stride = (long)gridDim.x * blockDim.x;
    for (; i < n4; i += stride) {
        float4 v = reinterpret_cast<const float4*>(in)[i];
        uint32_t hx = f2h(v.x), hy = f2h(v.y), hz = f2h(v.z), hw = f2h(v.w);
        reinterpret_cast<uint2*>(h)[i] = make_uint2(hx | (hy << 16), hz | (hw << 16));
    }
}

// ---------------- router (with fused dispatch scan) ----------------
__global__ void __launch_bounds__(256) router_kernel(
    const float* __restrict__ x, const int* __restrict__ mask,
    const float* __restrict__ noise, const float* __restrict__ Wr, int N, int D)
{
    int warp = threadIdx.x >> 5, lane = threadIdx.x & 31;
    int t = blockIdx.x * 8 + warp;
    __shared__ float s_log[8][16];
    __shared__ float s_p[16]; __shared__ int s_f[16];
    __shared__ float s_z; __shared__ int s_n;
    if (threadIdx.x < 16) { s_p[threadIdx.x] = 0.f; s_f[threadIdx.x] = 0; }
    if (threadIdx.x == 0) { s_z = 0.f; s_n = 0; }
    __syncthreads();
    if (t < N) {
        float acc[16];
#pragma unroll
        for (int e = 0; e < 16; ++e) acc[e] = 0.f;
        const float* xr = x + (size_t)t * D;
        for (int d = lane; d < D; d += 32) {
            float xv = xr[d];
            const float* w = Wr + (size_t)d * 16;
#pragma unroll
            for (int e = 0; e < 16; ++e) acc[e] = fmaf(xv, w[e], acc[e]);
        }
#pragma unroll
        for (int e = 0; e < 16; ++e) {
            float v = acc[e];
#pragma unroll
            for (int o = 16; o; o >>= 1) v += __shfl_xor_sync(0xFFFFFFFFu, v, o);
            if (lane == 0) s_log[warp][e] = v;
        }
        __syncwarp();
        int e = lane & 15;
        float lc = s_log[warp][e];
        int mk = mask[t] ? 1 : 0;
        float nz = noise[(size_t)t * 16 + e];
        float mult = mk ? (1.0f + (nz * 2.0f - 1.0f) * 0.1f) : 1.0f;
        float ln = lc * mult;
        float mx = ln;
#pragma unroll
        for (int o = 8; o; o >>= 1) mx = fmaxf(mx, __shfl_xor_sync(0xFFFFFFFFu, mx, o, 16));
        unsigned bal = __ballot_sync(0xFFFFFFFFu, ln == mx);
        int eid = __ffs(bal) - 1;
        float se = expf(ln - mx);
#pragma unroll
        for (int o = 8; o; o >>= 1) se += __shfl_xor_sync(0xFFFFFFFFu, se, o, 16);
        float lse = mx + logf(se);
        float gate = expf(mx - lse);
        float mxc = lc;
#pragma unroll
        for (int o = 8; o; o >>= 1) mxc = fmaxf(mxc, __shfl_xor_sync(0xFFFFFFFFu, mxc, o, 16));
        unsigned balc = __ballot_sync(0xFFFFFFFFu, lc == mxc);
        int eidc = __ffs(balc) - 1;
        float sec = expf(lc - mxc);
#pragma unroll
        for (int o = 8; o; o >>= 1) sec += __shfl_xor_sync(0xFFFFFFFFu, sec, o, 16);
        float lsec = mxc + logf(sec);
        float pce = expf(lc - lsec);
        if (lane < 16 && mk) {
            atomicAdd(&s_p[e], pce);
            if (e == eidc) atomicAdd(&s_f[e], 1);
        }
        if (lane == 0) {
            g_gate[t] = gate;
            if (mk) {
                atomicAdd(&s_z, lsec * lsec); atomicAdd(&s_n, 1);
                // fused dispatch scan: append token to expert eid's list
                int i = atomicAdd(&g_cnt[eid], 1);
                g_lst_tok[eid * NTOK + i] = t;
                g_lst_gate[eid * NTOK + i] = gate;
            }
        }
    }
    __syncthreads();
    if (threadIdx.x < 16) {
        g_pp[blockIdx.x * 16 + threadIdx.x] = s_p[threadIdx.x];
        g_pf[blockIdx.x * 16 + threadIdx.x] = s_f[threadIdx.x];
    }
    if (threadIdx.x == 0) { g_pz[blockIdx.x] = s_z; g_pn[blockIdx.x] = s_n; }
}

__global__ void loss_reduce_kernel(float* __restrict__ out, int nb, long outsz) {
    __shared__ float sp[16], sf[16], szn[2];
    int tid = threadIdx.x;
    if (tid < 16) {
        float s = 0.f; int c = 0;
        for (int b = 0; b < nb; ++b) { s += g_pp[b * 16 + tid]; c += g_pf[b * 16 + tid]; }
        sp[tid] = s; sf[tid] = (float)c;
    }
    if (tid == 16) { float s = 0.f; for (int b = 0; b < nb; ++b) s += g_pz[b]; szn[0] = s; }
    if (tid == 17) { int c = 0; for (int b = 0; b < nb; ++b) c += g_pn[b]; szn[1] = (float)c; }
    __syncthreads();
    if (tid == 0) {
        float n = szn[1], lb = 0.f;
        for (int e = 0; e < 16; ++e) lb += (sp[e] / n) * (sf[e] / n);
        out[outsz - 2] = lb * 16.0f;
        out[outsz - 1] = szn[0] / n;
    }
}

// ---------------- per-expert rank (top-cap by gate, lexsort semantics) ----------------
__global__ void __launch_bounds__(256) rank_kernel(int cap)
{
    extern __shared__ char dsm[];
    float* sg = (float*)dsm;
    int*   st = (int*)(dsm + (size_t)NTOK * 4);
    int e = blockIdx.x, tid = threadIdx.x;
    for (int i = tid; i < cap; i += 256) {
        g_tok4slot[e * cap + i] = -1;
        g_slotgate[e * cap + i] = 0.f;
    }
    int cnt = g_cnt[e];
    for (int i = tid; i < cnt; i += 256) {
        st[i] = g_lst_tok[e * NTOK + i];
        sg[i] = g_lst_gate[e * NTOK + i];
    }
    __syncthreads();
    for (int i = tid; i < cnt; i += 256) {
        int ti = st[i]; float gi = sg[i];
        int r = 0;
        for (int j = 0; j < cnt; ++j) {
            float gj = sg[j]; int tj = st[j];
            r += (gj > gi) || (gj == gi && tj < ti);
        }
        if (r < cap) {
            g_tok4slot[e * cap + r] = ti;
            g_slotgate[e * cap + r] = gi;
        }
    }
}

// ---------------- fp16 single-pass tensor-core GEMM, BK=64 ----------------
// CTA tile 128m x 128n, BK=64, 8 warps (4m x 2n), warp tile 32x64.
// 2-stage cp.async pipeline. Early-exit for m-tiles fully past g_cnt[e].
// MODE 0: h = relu(gather(x) @ W1[e]), KSPLIT=1, store epilogue.
// MODE 1: y += (h @ W2[e]) * gate over KSPLIT=4 segments, atomicAdd epilogue.
#define APITCH 144
#define STG (128 * APITCH + 64 * 256)   // 34816
#define ABUF(s) ((s) * STG)
#define BBUF(s) ((s) * STG + 128 * APITCH)
#define GSMEM (2 * STG)

template<int MODE, int KSPLIT>
__global__ void __launch_bounds__(256, 2) gemm_kernel(
    const float* __restrict__ xunused, float* __restrict__ y, int cap)
{
    const int KTOT = (MODE == 0) ? 1024 : 4096;
    const int KSEG = KTOT / KSPLIT;
    const int NT   = (MODE == 0) ? 32 : 8;
    const int Nn   = (MODE == 0) ? 4096 : 1024;
    const int NCH  = KSEG / 64;

    int b = blockIdx.x;
    const int m  = b % 5; b /= 5;
    const int n  = b % NT; b /= NT;
    const int kq = b % KSPLIT;
    const int e  = b / KSPLIT;
    const int m0 = m * 128, n0 = n * 128;

    // early exit: this m-tile has no routed tokens (all slots empty; outputs
    // would be discarded anyway)
    if (m0 >= g_cnt[e]) return;

    extern __shared__ char smem[];
    const uint32_t sb = smem_u32(smem);
    __shared__ int s_arow[128];

    const int tid = threadIdx.x, wid = tid >> 5, lane = tid & 31;
    const int wm = wid & 3, wn = wid >> 2;

    if (tid < 128) {
        if (MODE == 0) {
            int tok = g_tok4slot[e * cap + m0 + tid];
            s_arow[tid] = (tok >= 0) ? tok : 0;
        } else {
            s_arow[tid] = e * CAPS + m0 + tid;
        }
    }
    __syncthreads();

    const ushort_t* AH = ((MODE == 0) ? g_xh : g_hh) + (size_t)kq * KSEG;
    const ushort_t* BH = ((MODE == 0) ? g_w1h : g_w2h)
                         + (size_t)e * KTOT * Nn + (size_t)kq * KSEG * Nn;

    // per-thread cp.async coordinates: 4 slots each for A and B
    const ushort_t* aP[4];
    const ushort_t* bP[4];
    uint32_t aOff[4], bOff[4];
#pragma unroll
    for (int i = 0; i < 4; ++i) {
        int ia = tid + i * 256;
        int ar = ia >> 3, ac = ia & 7;
        aP[i] = AH + (size_t)s_arow[ar] * KTOT + ac * 8;
        aOff[i] = ar * APITCH + ac * 16;
        int br = ia >> 4, bc = ia & 15;
        bP[i] = BH + (size_t)br * Nn + n0 + bc * 8;
        bOff[i] = br * 256 + ((bc ^ (br & 7)) << 4);
    }

    float acc[2][8][4];
#pragma unroll
    for (int i = 0; i < 2; ++i)
#pragma unroll
        for (int j = 0; j < 8; ++j)
#pragma unroll
            for (int q = 0; q < 4; ++q) acc[i][j][q] = 0.f;

    auto issue = [&](int kt, int buf) {
        const long ka = (long)kt * 64;
        const long kb = (long)kt * 64 * Nn;
#pragma unroll
        for (int i = 0; i < 4; ++i) cpa16(sb + ABUF(buf) + aOff[i], aP[i] + ka);
#pragma unroll
        for (int i = 0; i < 4; ++i) cpa16(sb + BBUF(buf) + bOff[i], bP[i] + kb);
        cp_commit();
    };

    issue(0, 0);

    const uint32_t a_row = (lane & 15), a_kq = (lane >> 4);
    const uint32_t b_kr = (lane & 7) + (lane >> 4) * 8;
    const uint32_t b_nc = wn * 8 + ((lane >> 3) & 1);

    for (int kt = 0; kt < NCH; ++kt) {
        const int buf = kt & 1;
        if (kt + 1 < NCH) { issue(kt + 1, buf ^ 1); cp_wait1(); }
        else cp_wait0();
        __syncthreads();

        const uint32_t aB = sb + ABUF(buf);
        const uint32_t bB = sb + BBUF(buf);

#pragma unroll
        for (int ks = 0; ks < 4; ++ks) {
            uint32_t fA[2][4];
#pragma unroll
            for (int tm = 0; tm < 2; ++tm) {
                uint32_t ao = (wm * 32 + tm * 16 + a_row) * APITCH + (ks * 16 + a_kq * 8) * 2;
                ldsm4(fA[tm], aB + ao);
            }
            const uint32_t kr = ks * 16 + b_kr;
            const uint32_t krl = kr & 7;
#pragma unroll
            for (int nb = 0; nb < 4; ++nb) {
                uint32_t nc = b_nc + nb * 2;
                uint32_t bo = kr * 256 + ((nc ^ krl) << 4);
                uint32_t fB[4];
                ldsm4t(fB, bB + bo);
#pragma unroll
                for (int tm = 0; tm < 2; ++tm) {
                    mmaf16(acc[tm][nb * 2 + 0], fA[tm], fB[0], fB[2]);
                    mmaf16(acc[tm][nb * 2 + 1], fA[tm], fB[1], fB[3]);
                }
            }
        }
        __syncthreads();
    }

    // ---- epilogue ----
    const int gid = lane >> 2, tig = lane & 3;
#pragma unroll
    for (int tm = 0; tm < 2; ++tm) {
        const int r0 = m0 + wm * 32 + tm * 16 + gid;
#pragma unroll
        for (int j = 0; j < 8; ++j) {
            const int col = n0 + wn * 64 + j * 8 + tig * 2;
            if (MODE == 0) {
#pragma unroll
                for (int hh = 0; hh < 2; ++hh) {
                    int row = r0 + hh * 8;
                    float v0 = fmaxf(acc[tm][j][hh * 2 + 0], 0.f);
                    float v1 = fmaxf(acc[tm][j][hh * 2 + 1], 0.f);
                    uint32_t h0 = f2h(v0), h1 = f2h(v1);
                    size_t idx = (size_t)(e * CAPS + row) * 4096 + col;
                    *(uint32_t*)(g_hh + idx) = h0 | (h1 << 16);
                }
            } else {
#pragma unroll
                for (int hh = 0; hh < 2; ++hh) {
                    int row = r0 + hh * 8;
                    int slot = e * cap + row;
                    int tok = g_tok4slot[slot];
                    if (tok >= 0) {
                        float g = g_slotgate[slot];
                        float* dst = y + (size_t)tok * 1024 + col;
                        atomicAdd(dst + 0, acc[tm][j][hh * 2 + 0] * g);
                        atomicAdd(dst + 1, acc[tm][j][hh * 2 + 1] * g);
                    }
                }
            }
        }
    }
}

// ---------------- launch ----------------
extern "C" void kernel_launch(void* const* d_in, const int* in_sizes, int n_in,
                              void* d_out, int out_size)
{
    const float* x     = (const float*)d_in[0];
    const int*   mask  = (const int*)d_in[1];
    const float* noise = (const float*)d_in[2];
    const float* Wr    = (const float*)d_in[3];
    const float* W1    = (const float*)d_in[4];
    const float* W2    = (const float*)d_in[5];
    float*       out   = (float*)d_out;

    const int  N = in_sizes[1];                      // 8192
    const int  D = in_sizes[0] / N;                  // 1024
    const int  E = in_sizes[2] / N;                  // 16
    const int  H = (int)((long)in_sizes[4] / ((long)E * D)); // 4096
    const int  cap = (int)((long)N * 5 / (4 * E));   // 640
    const long ytot = (long)N * D;

    cudaFuncSetAttribute((const void*)gemm_kernel<0,1>, cudaFuncAttributeMaxDynamicSharedMemorySize, GSMEM);
    cudaFuncSetAttribute((const void*)gemm_kernel<1,4>, cudaFuncAttributeMaxDynamicSharedMemorySize, GSMEM);
    cudaFuncSetAttribute(rank_kernel, cudaFuncAttributeMaxDynamicSharedMemorySize, 65536);

    init_kernel<<<(unsigned)((ytot / 4 + 255) / 256), 256>>>(out, ytot);
    router_kernel<<<N / 8, 256>>>(x, mask, noise, Wr, N, D);
    loss_reduce_kernel<<<1, 32>>>(out, N / 8, (long)out_size);
    rank_kernel<<<E, 256, (size_t)N * 8>>>(cap);

    ushort_t *xh, *w1h, *w2h;
    cudaGetSymbolAddress((void**)&xh, g_xh);
    cudaGetSymbolAddress((void**)&w1h, g_w1h);
    cudaGetSymbolAddress((void**)&w2h, g_w2h);

    pack_kernel<<<2048, 256>>>(x, xh, (long)N * D / 4);
    pack_kernel<<<4096, 256>>>(W1, w1h, (long)E * D * H / 4);
    pack_kernel<<<4096, 256>>>(W2, w2h, (long)E * D * H / 4);

    gemm_kernel<0,1><<<E * (H / 128) * 5, 256, GSMEM>>>(x, out, cap);
    gemm_kernel<1,4><<<E * (D / 128) * 5 * 4, 256, GSMEM>>>(x, out, cap);
}